// round 1
// baseline (speedup 1.0000x reference)
#include <cuda_runtime.h>
#include <math.h>

// Problem constants
#define BB  2
#define LL  2048
#define DDM 1024
#define HH  16
#define DKK 64
#define MMR (BB * LL)      // 4096 rows for all GEMMs

// Scratch (device globals; no allocation allowed)
__device__ float g_q[(size_t)MMR * DDM];
__device__ float g_k[(size_t)MMR * DDM];
__device__ float g_v[(size_t)MMR * DDM];
__device__ float g_attn[(size_t)MMR * DDM];

// ---------------------------------------------------------------------------
// GEMM: C[m,n] = sum_k A[m,k] * W[n,k] + bias[n]
// A: [M=4096, K=1024] row-major.  W: [N=1024, K=1024] row-major (torch Linear).
// 128x128x16 tile, 256 threads, 8x8 microtile (split {0,64} halves so fragment
// loads are contiguous float4 across tx -> conflict-free).
// ---------------------------------------------------------------------------
__device__ __forceinline__ void gemm_tile(
    const float* __restrict__ A, const float* __restrict__ W,
    const float* __restrict__ bias, float* __restrict__ C)
{
    const int K = DDM, N = DDM;
    __shared__ float As[16][132];   // [k][m], padded
    __shared__ float Bs[16][132];   // [k][n], padded

    const int tid = threadIdx.x;
    const int tx = tid & 15, ty = tid >> 4;
    const int m0 = blockIdx.y * 128;
    const int n0 = blockIdx.x * 128;

    float acc[8][8];
#pragma unroll
    for (int i = 0; i < 8; i++)
#pragma unroll
        for (int j = 0; j < 8; j++) acc[i][j] = 0.f;

    for (int kt = 0; kt < K; kt += 16) {
#pragma unroll
        for (int i = 0; i < 2; i++) {
            int id  = tid + i * 256;           // [0, 512)
            int row = id >> 2;                 // [0, 128)
            int kq  = (id & 3) << 2;           // {0,4,8,12}
            float4 a = *(const float4*)&A[(size_t)(m0 + row) * K + kt + kq];
            As[kq + 0][row] = a.x; As[kq + 1][row] = a.y;
            As[kq + 2][row] = a.z; As[kq + 3][row] = a.w;
            float4 b = *(const float4*)&W[(size_t)(n0 + row) * K + kt + kq];
            Bs[kq + 0][row] = b.x; Bs[kq + 1][row] = b.y;
            Bs[kq + 2][row] = b.z; Bs[kq + 3][row] = b.w;
        }
        __syncthreads();
#pragma unroll
        for (int k = 0; k < 16; k++) {
            float4 a0 = *(const float4*)&As[k][ty * 4];
            float4 a1 = *(const float4*)&As[k][64 + ty * 4];
            float4 b0 = *(const float4*)&Bs[k][tx * 4];
            float4 b1 = *(const float4*)&Bs[k][64 + tx * 4];
            float am[8] = {a0.x, a0.y, a0.z, a0.w, a1.x, a1.y, a1.z, a1.w};
            float bn[8] = {b0.x, b0.y, b0.z, b0.w, b1.x, b1.y, b1.z, b1.w};
#pragma unroll
            for (int i = 0; i < 8; i++)
#pragma unroll
                for (int j = 0; j < 8; j++)
                    acc[i][j] += am[i] * bn[j];
        }
        __syncthreads();
    }

#pragma unroll
    for (int i = 0; i < 8; i++) {
        int m = m0 + ((i < 4) ? (ty * 4 + i) : (64 + ty * 4 + (i - 4)));
#pragma unroll
        for (int jh = 0; jh < 2; jh++) {
            int n = n0 + jh * 64 + tx * 4;
            float4 bv = *(const float4*)&bias[n];
            float4 o;
            o.x = acc[i][jh * 4 + 0] + bv.x;
            o.y = acc[i][jh * 4 + 1] + bv.y;
            o.z = acc[i][jh * 4 + 2] + bv.z;
            o.w = acc[i][jh * 4 + 3] + bv.w;
            *(float4*)&C[(size_t)m * N + n] = o;
        }
    }
}

__global__ __launch_bounds__(256) void qkv_proj_kernel(
    const float* __restrict__ Q, const float* __restrict__ Kin, const float* __restrict__ Vin,
    const float* __restrict__ Wq, const float* __restrict__ Wk, const float* __restrict__ Wv,
    const float* __restrict__ bq, const float* __restrict__ bk, const float* __restrict__ bv)
{
    if (blockIdx.z == 0)      gemm_tile(Q,   Wq, bq, g_q);
    else if (blockIdx.z == 1) gemm_tile(Kin, Wk, bk, g_k);
    else                      gemm_tile(Vin, Wv, bv, g_v);
}

__global__ __launch_bounds__(256) void out_proj_kernel(
    const float* __restrict__ Wo, const float* __restrict__ bo, float* __restrict__ out)
{
    gemm_tile(g_attn, Wo, bo, out);
}

// ---------------------------------------------------------------------------
// Flash attention (causal). One CTA = one (b, h, 64 q-rows) tile.
// Threads: 16x16; each thread owns a 4x4 microtile (rows ty*4.., cols tx*4..).
// Smem: Qs [64][68] row-major(q,d); Kt [64][68] d-major(d,col) -> contiguous
// float4 reads across tx; Vs [64][68] row-major(c,d); Ss [64][68] probs.
// ---------------------------------------------------------------------------
#define SMS 68
#define ATTN_SMEM (4 * 64 * SMS * sizeof(float))

__global__ __launch_bounds__(256) void attn_kernel()
{
    extern __shared__ float sm[];
    float* Qs = sm;
    float* Kt = Qs + 64 * SMS;
    float* Vs = Kt + 64 * SMS;
    float* Ss = Vs + 64 * SMS;

    const int tid = threadIdx.x;
    const int tx = tid & 15, ty = tid >> 4;
    const int qt = gridDim.x - 1 - blockIdx.x;     // big (late) tiles first
    const int bh = blockIdx.y;
    const int b = bh >> 4, h = bh & 15;
    const int qbase = qt * 64;

    const float* qg = g_q + (size_t)b * LL * DDM + (size_t)h * DKK;
    const float* kg = g_k + (size_t)b * LL * DDM + (size_t)h * DKK;
    const float* vg = g_v + (size_t)b * LL * DDM + (size_t)h * DKK;

    // Load Q tile [64 rows][64 d]
#pragma unroll
    for (int i = 0; i < 4; i++) {
        int id  = tid + i * 256;
        int row = id >> 4;
        int dq  = (id & 15) << 2;
        float4 q = *(const float4*)&qg[(size_t)(qbase + row) * DDM + dq];
        *(float4*)&Qs[row * SMS + dq] = q;
    }

    float m_r[4], l_r[4], o[4][4];
#pragma unroll
    for (int r = 0; r < 4; r++) {
        m_r[r] = -INFINITY; l_r[r] = 0.f;
#pragma unroll
        for (int j = 0; j < 4; j++) o[r][j] = 0.f;
    }

    for (int kt = 0; kt <= qt; kt++) {
        const int kbase = kt * 64;
        __syncthreads();   // Q ready (first iter) / prior PV & loads done

        // Load K (store d-major transposed) and V (row-major)
#pragma unroll
        for (int i = 0; i < 4; i++) {
            int id  = tid + i * 256;
            int row = id >> 4;
            int dq  = (id & 15) << 2;
            float4 kk = *(const float4*)&kg[(size_t)(kbase + row) * DDM + dq];
            Kt[(dq + 0) * SMS + row] = kk.x;
            Kt[(dq + 1) * SMS + row] = kk.y;
            Kt[(dq + 2) * SMS + row] = kk.z;
            Kt[(dq + 3) * SMS + row] = kk.w;
            float4 vv = *(const float4*)&vg[(size_t)(kbase + row) * DDM + dq];
            *(float4*)&Vs[row * SMS + dq] = vv;
        }
        __syncthreads();

        // S = Q K^T (4x4 per thread)
        float s[4][4];
#pragma unroll
        for (int r = 0; r < 4; r++)
#pragma unroll
            for (int c = 0; c < 4; c++) s[r][c] = 0.f;

#pragma unroll
        for (int d4 = 0; d4 < 16; d4++) {
            float qreg[4][4], kreg[4][4];
#pragma unroll
            for (int r = 0; r < 4; r++) {
                float4 q = *(const float4*)&Qs[(ty * 4 + r) * SMS + d4 * 4];
                qreg[r][0] = q.x; qreg[r][1] = q.y; qreg[r][2] = q.z; qreg[r][3] = q.w;
            }
#pragma unroll
            for (int dd = 0; dd < 4; dd++) {
                float4 k = *(const float4*)&Kt[(d4 * 4 + dd) * SMS + tx * 4];
                kreg[dd][0] = k.x; kreg[dd][1] = k.y; kreg[dd][2] = k.z; kreg[dd][3] = k.w;
            }
#pragma unroll
            for (int r = 0; r < 4; r++)
#pragma unroll
                for (int c = 0; c < 4; c++)
#pragma unroll
                    for (int dd = 0; dd < 4; dd++)
                        s[r][c] += qreg[r][dd] * kreg[dd][c];
        }

#pragma unroll
        for (int r = 0; r < 4; r++)
#pragma unroll
            for (int c = 0; c < 4; c++) s[r][c] *= 0.125f;  // 1/sqrt(64)

        if (kt == qt) {
#pragma unroll
            for (int r = 0; r < 4; r++)
#pragma unroll
                for (int c = 0; c < 4; c++)
                    if (kbase + tx * 4 + c > qbase + ty * 4 + r)
                        s[r][c] = -INFINITY;
        }

        // Online softmax; row reduction across the 16 tx lanes (same warp half)
#pragma unroll
        for (int r = 0; r < 4; r++) {
            float mx = fmaxf(fmaxf(s[r][0], s[r][1]), fmaxf(s[r][2], s[r][3]));
#pragma unroll
            for (int off = 8; off >= 1; off >>= 1)
                mx = fmaxf(mx, __shfl_xor_sync(0xffffffffu, mx, off));
            float mnew = fmaxf(m_r[r], mx);
            float p0 = __expf(s[r][0] - mnew);
            float p1 = __expf(s[r][1] - mnew);
            float p2 = __expf(s[r][2] - mnew);
            float p3 = __expf(s[r][3] - mnew);
            float sum = (p0 + p1) + (p2 + p3);
#pragma unroll
            for (int off = 8; off >= 1; off >>= 1)
                sum += __shfl_xor_sync(0xffffffffu, sum, off);
            float alpha = __expf(m_r[r] - mnew);
            l_r[r] = l_r[r] * alpha + sum;
            m_r[r] = mnew;
#pragma unroll
            for (int j = 0; j < 4; j++) o[r][j] *= alpha;
            float4 pv = make_float4(p0, p1, p2, p3);
            *(float4*)&Ss[(ty * 4 + r) * SMS + tx * 4] = pv;
        }
        __syncthreads();

        // O += P V
#pragma unroll
        for (int c4 = 0; c4 < 16; c4++) {
            float preg[4][4], vreg[4][4];
#pragma unroll
            for (int r = 0; r < 4; r++) {
                float4 p = *(const float4*)&Ss[(ty * 4 + r) * SMS + c4 * 4];
                preg[r][0] = p.x; preg[r][1] = p.y; preg[r][2] = p.z; preg[r][3] = p.w;
            }
#pragma unroll
            for (int cc = 0; cc < 4; cc++) {
                float4 v = *(const float4*)&Vs[(c4 * 4 + cc) * SMS + tx * 4];
                vreg[cc][0] = v.x; vreg[cc][1] = v.y; vreg[cc][2] = v.z; vreg[cc][3] = v.w;
            }
#pragma unroll
            for (int r = 0; r < 4; r++)
#pragma unroll
                for (int d = 0; d < 4; d++)
#pragma unroll
                    for (int cc = 0; cc < 4; cc++)
                        o[r][d] += preg[r][cc] * vreg[cc][d];
        }
    }

    // Normalize and store: g_attn is [B, L, D] with head h at column h*64
    float* og = g_attn + (size_t)b * LL * DDM + (size_t)h * DKK;
#pragma unroll
    for (int r = 0; r < 4; r++) {
        float inv = 1.0f / l_r[r];
        float4 res = make_float4(o[r][0] * inv, o[r][1] * inv,
                                 o[r][2] * inv, o[r][3] * inv);
        *(float4*)&og[(size_t)(qbase + ty * 4 + r) * DDM + tx * 4] = res;
    }
}

// ---------------------------------------------------------------------------
// Inputs (metadata order): Q, K, V, mask, Wq, bq, Wk, bk, Wv, bv, Wo, bo.
// mask (d_in[3]) is known-causal; ignored.
// ---------------------------------------------------------------------------
extern "C" void kernel_launch(void* const* d_in, const int* in_sizes, int n_in,
                              void* d_out, int out_size)
{
    const float* Q  = (const float*)d_in[0];
    const float* K  = (const float*)d_in[1];
    const float* V  = (const float*)d_in[2];
    const float* Wq = (const float*)d_in[4];
    const float* bq = (const float*)d_in[5];
    const float* Wk = (const float*)d_in[6];
    const float* bk = (const float*)d_in[7];
    const float* Wv = (const float*)d_in[8];
    const float* bv = (const float*)d_in[9];
    const float* Wo = (const float*)d_in[10];
    const float* bo = (const float*)d_in[11];
    float* out = (float*)d_out;

    cudaFuncSetAttribute(attn_kernel,
                         cudaFuncAttributeMaxDynamicSharedMemorySize,
                         (int)ATTN_SMEM);

    dim3 gproj(DDM / 128, MMR / 128, 3);
    qkv_proj_kernel<<<gproj, 256>>>(Q, K, V, Wq, Wk, Wv, bq, bk, bv);

    dim3 gattn(LL / 64, BB * HH);
    attn_kernel<<<gattn, 256, ATTN_SMEM>>>();

    dim3 gout(DDM / 128, MMR / 128);
    out_proj_kernel<<<gout, 256>>>(Wo, bo, out);
}

// round 3
// speedup vs baseline: 1.3192x; 1.3192x over previous
#include <cuda_runtime.h>
#include <cuda_fp16.h>
#include <mma.h>
#include <math.h>
#include <stdint.h>

using namespace nvcuda;

// Problem constants
#define BB  2
#define LL  2048
#define DDM 1024
#define HH  16
#define DKK 64
#define MMR (BB * LL)      // 4096 rows

// ---------------- scratch (device globals; no allocation allowed) ----------
__device__ float g_q[(size_t)MMR * DDM];
__device__ float g_k[(size_t)MMR * DDM];
__device__ float g_v[(size_t)MMR * DDM];
__device__ float g_attn[(size_t)MMR * DDM];

// fp16 hi/lo split buffers
__device__ __half g_qh[(size_t)MMR * DDM], g_ql[(size_t)MMR * DDM];
__device__ __half g_kh[(size_t)MMR * DDM], g_kl[(size_t)MMR * DDM];
__device__ __half g_vh[(size_t)MMR * DDM], g_vl[(size_t)MMR * DDM];
__device__ __half g_ah[(size_t)MMR * DDM], g_al[(size_t)MMR * DDM];
__device__ __half g_wqh[(size_t)DDM * DDM], g_wql[(size_t)DDM * DDM];
__device__ __half g_wkh[(size_t)DDM * DDM], g_wkl[(size_t)DDM * DDM];
__device__ __half g_wvh[(size_t)DDM * DDM], g_wvl[(size_t)DDM * DDM];
__device__ __half g_woh[(size_t)DDM * DDM], g_wol[(size_t)DDM * DDM];

// ---------------- fp32 -> fp16 hi/lo split conversion ----------------------
// which: 0..2 -> Q,K,V inputs; 3..6 -> Wq,Wk,Wv,Wo; 7 -> g_attn
__global__ __launch_bounds__(256) void cvt_kernel(const float* __restrict__ x,
                                                  int which, int n4)
{
    __half *hi, *lo;
    switch (which) {
        case 0: hi = g_qh;  lo = g_ql;  break;
        case 1: hi = g_kh;  lo = g_kl;  break;
        case 2: hi = g_vh;  lo = g_vl;  break;
        case 3: hi = g_wqh; lo = g_wql; break;
        case 4: hi = g_wkh; lo = g_wkl; break;
        case 5: hi = g_wvh; lo = g_wvl; break;
        case 6: hi = g_woh; lo = g_wol; break;
        default: hi = g_ah; lo = g_al; x = g_attn; break;
    }
    int i = blockIdx.x * blockDim.x + threadIdx.x;
    if (i >= n4) return;
    float4 v = ((const float4*)x)[i];
    __half h0 = __float2half(v.x);
    __half h1 = __float2half(v.y);
    __half h2 = __float2half(v.z);
    __half h3 = __float2half(v.w);
    __half l0 = __float2half(v.x - __half2float(h0));
    __half l1 = __float2half(v.y - __half2float(h1));
    __half l2 = __float2half(v.z - __half2float(h2));
    __half l3 = __float2half(v.w - __half2float(h3));
    __half2* hp = (__half2*)hi;
    __half2* lp = (__half2*)lo;
    hp[i * 2 + 0] = __halves2half2(h0, h1);
    hp[i * 2 + 1] = __halves2half2(h2, h3);
    lp[i * 2 + 0] = __halves2half2(l0, l1);
    lp[i * 2 + 1] = __halves2half2(l2, l3);
}

// ---------------- WMMA GEMM: C = (Ah+Al)(Wh+Wl)^T + bias -------------------
// A: [4096,1024] row-major.  W: [1024,1024] row-major (torch Linear).
// CTA tile 128x128, 8 warps, each warp 32x64 (2x4 wmma 16x16 tiles).
// K chunks of 64; smem ld = 72 halves (conflict-free LDSM).
// 3 mma combos per product: AhWh + AhWl + AlWh  (error ~2^-22).
#define LDH 72
#define A_TILE (128 * LDH)               // halves
#define SMEM_GEMM_BYTES (4 * A_TILE * 2) // 73728 bytes

__device__ __forceinline__ void wmma_gemm(
    const __half* __restrict__ Ah, const __half* __restrict__ Al,
    const __half* __restrict__ Wh, const __half* __restrict__ Wl,
    const float* __restrict__ bias, float* __restrict__ C)
{
    extern __shared__ char smem[];
    __half* sAh = (__half*)smem;
    __half* sAl = sAh + A_TILE;
    __half* sWh = sAl + A_TILE;
    __half* sWl = sWh + A_TILE;

    const int tid  = threadIdx.x;
    const int w    = tid >> 5, lane = tid & 31;
    const int wm   = w & 3, wn = w >> 2;   // 4x2 warp grid
    const int m0   = blockIdx.y * 128;
    const int n0   = blockIdx.x * 128;

    wmma::fragment<wmma::accumulator, 16, 16, 16, float> acc[2][4];
#pragma unroll
    for (int i = 0; i < 2; i++)
#pragma unroll
        for (int j = 0; j < 4; j++) wmma::fill_fragment(acc[i][j], 0.0f);

    const __half* srcs[4] = {Ah, Al, Wh, Wl};
    __half* dsts[4] = {sAh, sAl, sWh, sWl};

    for (int c = 0; c < 16; c++) {
        const int k0 = c * 64;
        // global -> regs (16 x float4 = 16 x 8 halves per thread)
        float4 buf[16];
#pragma unroll
        for (int t = 0; t < 4; t++) {
            const __half* src = srcs[t];
            const int rb = (t < 2) ? m0 : n0;
#pragma unroll
            for (int i = 0; i < 4; i++) {
                int id = i * 256 + tid;
                int r = id >> 3, q = id & 7;
                buf[t * 4 + i] =
                    *(const float4*)&src[(size_t)(rb + r) * DDM + k0 + q * 8];
            }
        }
        __syncthreads();   // previous chunk's compute done
#pragma unroll
        for (int t = 0; t < 4; t++) {
#pragma unroll
            for (int i = 0; i < 4; i++) {
                int id = i * 256 + tid;
                int r = id >> 3, q = id & 7;
                *(float4*)&dsts[t][r * LDH + q * 8] = buf[t * 4 + i];
            }
        }
        __syncthreads();

#pragma unroll
        for (int kk = 0; kk < 4; kk++) {
            wmma::fragment<wmma::matrix_a, 16, 16, 16, __half, wmma::row_major> a_h[2], a_l[2];
#pragma unroll
            for (int i = 0; i < 2; i++) {
                const int ro = (wm * 32 + i * 16) * LDH + kk * 16;
                wmma::load_matrix_sync(a_h[i], sAh + ro, LDH);
                wmma::load_matrix_sync(a_l[i], sAl + ro, LDH);
            }
#pragma unroll
            for (int j = 0; j < 4; j++) {
                wmma::fragment<wmma::matrix_b, 16, 16, 16, __half, wmma::col_major> b_h, b_l;
                const int co = (wn * 64 + j * 16) * LDH + kk * 16;
                wmma::load_matrix_sync(b_h, sWh + co, LDH);
                wmma::load_matrix_sync(b_l, sWl + co, LDH);
#pragma unroll
                for (int i = 0; i < 2; i++) {
                    wmma::mma_sync(acc[i][j], a_h[i], b_h, acc[i][j]);
                    wmma::mma_sync(acc[i][j], a_h[i], b_l, acc[i][j]);
                    wmma::mma_sync(acc[i][j], a_l[i], b_h, acc[i][j]);
                }
            }
        }
    }

    // Epilogue: stage through smem, add bias, vectorized global store.
    __syncthreads();
    float* stage = (float*)smem + w * (32 * 68);
#pragma unroll
    for (int i = 0; i < 2; i++)
#pragma unroll
        for (int j = 0; j < 4; j++)
            wmma::store_matrix_sync(stage + i * 16 * 68 + j * 16, acc[i][j],
                                    68, wmma::mem_row_major);
    __syncwarp();

    const int col4 = (lane & 15) * 4;
    const int rb   = lane >> 4;
    const int ng   = n0 + wn * 64 + col4;
    float4 b4 = *(const float4*)&bias[ng];
#pragma unroll
    for (int r = 0; r < 16; r++) {
        int row = rb + r * 2;
        float4 v = *(float4*)&stage[row * 68 + col4];
        v.x += b4.x; v.y += b4.y; v.z += b4.z; v.w += b4.w;
        *(float4*)&C[(size_t)(m0 + wm * 32 + row) * DDM + ng] = v;
    }
}

__global__ __launch_bounds__(256) void qkv_wmma_kernel(
    const float* __restrict__ bq, const float* __restrict__ bk,
    const float* __restrict__ bv)
{
    if (blockIdx.z == 0)      wmma_gemm(g_qh, g_ql, g_wqh, g_wql, bq, g_q);
    else if (blockIdx.z == 1) wmma_gemm(g_kh, g_kl, g_wkh, g_wkl, bk, g_k);
    else                      wmma_gemm(g_vh, g_vl, g_wvh, g_wvl, bv, g_v);
}

__global__ __launch_bounds__(256) void out_wmma_kernel(
    const float* __restrict__ bo, float* __restrict__ out)
{
    wmma_gemm(g_ah, g_al, g_woh, g_wol, bo, out);
}

// ---------------------------------------------------------------------------
// Flash attention (causal), fp32 — unchanged (known good).
// ---------------------------------------------------------------------------
#define SMS 68
#define ATTN_SMEM (4 * 64 * SMS * sizeof(float))

__global__ __launch_bounds__(256) void attn_kernel()
{
    extern __shared__ float sm[];
    float* Qs = sm;
    float* Kt = Qs + 64 * SMS;
    float* Vs = Kt + 64 * SMS;
    float* Ss = Vs + 64 * SMS;

    const int tid = threadIdx.x;
    const int tx = tid & 15, ty = tid >> 4;
    const int qt = gridDim.x - 1 - blockIdx.x;
    const int bh = blockIdx.y;
    const int b = bh >> 4, h = bh & 15;
    const int qbase = qt * 64;

    const float* qg = g_q + (size_t)b * LL * DDM + (size_t)h * DKK;
    const float* kg = g_k + (size_t)b * LL * DDM + (size_t)h * DKK;
    const float* vg = g_v + (size_t)b * LL * DDM + (size_t)h * DKK;

#pragma unroll
    for (int i = 0; i < 4; i++) {
        int id  = tid + i * 256;
        int row = id >> 4;
        int dq  = (id & 15) << 2;
        float4 q = *(const float4*)&qg[(size_t)(qbase + row) * DDM + dq];
        *(float4*)&Qs[row * SMS + dq] = q;
    }

    float m_r[4], l_r[4], o[4][4];
#pragma unroll
    for (int r = 0; r < 4; r++) {
        m_r[r] = -INFINITY; l_r[r] = 0.f;
#pragma unroll
        for (int j = 0; j < 4; j++) o[r][j] = 0.f;
    }

    for (int kt = 0; kt <= qt; kt++) {
        const int kbase = kt * 64;
        __syncthreads();

#pragma unroll
        for (int i = 0; i < 4; i++) {
            int id  = tid + i * 256;
            int row = id >> 4;
            int dq  = (id & 15) << 2;
            float4 kk = *(const float4*)&kg[(size_t)(kbase + row) * DDM + dq];
            Kt[(dq + 0) * SMS + row] = kk.x;
            Kt[(dq + 1) * SMS + row] = kk.y;
            Kt[(dq + 2) * SMS + row] = kk.z;
            Kt[(dq + 3) * SMS + row] = kk.w;
            float4 vv = *(const float4*)&vg[(size_t)(kbase + row) * DDM + dq];
            *(float4*)&Vs[row * SMS + dq] = vv;
        }
        __syncthreads();

        float s[4][4];
#pragma unroll
        for (int r = 0; r < 4; r++)
#pragma unroll
            for (int c = 0; c < 4; c++) s[r][c] = 0.f;

#pragma unroll
        for (int d4 = 0; d4 < 16; d4++) {
            float qreg[4][4], kreg[4][4];
#pragma unroll
            for (int r = 0; r < 4; r++) {
                float4 q = *(const float4*)&Qs[(ty * 4 + r) * SMS + d4 * 4];
                qreg[r][0] = q.x; qreg[r][1] = q.y; qreg[r][2] = q.z; qreg[r][3] = q.w;
            }
#pragma unroll
            for (int dd = 0; dd < 4; dd++) {
                float4 k = *(const float4*)&Kt[(d4 * 4 + dd) * SMS + tx * 4];
                kreg[dd][0] = k.x; kreg[dd][1] = k.y; kreg[dd][2] = k.z; kreg[dd][3] = k.w;
            }
#pragma unroll
            for (int r = 0; r < 4; r++)
#pragma unroll
                for (int c = 0; c < 4; c++)
#pragma unroll
                    for (int dd = 0; dd < 4; dd++)
                        s[r][c] += qreg[r][dd] * kreg[dd][c];
        }

#pragma unroll
        for (int r = 0; r < 4; r++)
#pragma unroll
            for (int c = 0; c < 4; c++) s[r][c] *= 0.125f;

        if (kt == qt) {
#pragma unroll
            for (int r = 0; r < 4; r++)
#pragma unroll
                for (int c = 0; c < 4; c++)
                    if (kbase + tx * 4 + c > qbase + ty * 4 + r)
                        s[r][c] = -INFINITY;
        }

#pragma unroll
        for (int r = 0; r < 4; r++) {
            float mx = fmaxf(fmaxf(s[r][0], s[r][1]), fmaxf(s[r][2], s[r][3]));
#pragma unroll
            for (int off = 8; off >= 1; off >>= 1)
                mx = fmaxf(mx, __shfl_xor_sync(0xffffffffu, mx, off));
            float mnew = fmaxf(m_r[r], mx);
            float p0 = __expf(s[r][0] - mnew);
            float p1 = __expf(s[r][1] - mnew);
            float p2 = __expf(s[r][2] - mnew);
            float p3 = __expf(s[r][3] - mnew);
            float sum = (p0 + p1) + (p2 + p3);
#pragma unroll
            for (int off = 8; off >= 1; off >>= 1)
                sum += __shfl_xor_sync(0xffffffffu, sum, off);
            float alpha = __expf(m_r[r] - mnew);
            l_r[r] = l_r[r] * alpha + sum;
            m_r[r] = mnew;
#pragma unroll
            for (int j = 0; j < 4; j++) o[r][j] *= alpha;
            float4 pv = make_float4(p0, p1, p2, p3);
            *(float4*)&Ss[(ty * 4 + r) * SMS + tx * 4] = pv;
        }
        __syncthreads();

#pragma unroll
        for (int c4 = 0; c4 < 16; c4++) {
            float preg[4][4], vreg[4][4];
#pragma unroll
            for (int r = 0; r < 4; r++) {
                float4 p = *(const float4*)&Ss[(ty * 4 + r) * SMS + c4 * 4];
                preg[r][0] = p.x; preg[r][1] = p.y; preg[r][2] = p.z; preg[r][3] = p.w;
            }
#pragma unroll
            for (int cc = 0; cc < 4; cc++) {
                float4 v = *(const float4*)&Vs[(c4 * 4 + cc) * SMS + tx * 4];
                vreg[cc][0] = v.x; vreg[cc][1] = v.y; vreg[cc][2] = v.z; vreg[cc][3] = v.w;
            }
#pragma unroll
            for (int r = 0; r < 4; r++)
#pragma unroll
                for (int d = 0; d < 4; d++)
#pragma unroll
                    for (int cc = 0; cc < 4; cc++)
                        o[r][d] += preg[r][cc] * vreg[cc][d];
        }
    }

    float* og = g_attn + (size_t)b * LL * DDM + (size_t)h * DKK;
#pragma unroll
    for (int r = 0; r < 4; r++) {
        float inv = 1.0f / l_r[r];
        float4 res = make_float4(o[r][0] * inv, o[r][1] * inv,
                                 o[r][2] * inv, o[r][3] * inv);
        *(float4*)&og[(size_t)(qbase + ty * 4 + r) * DDM + tx * 4] = res;
    }
}

// ---------------------------------------------------------------------------
// Inputs (metadata order): Q, K, V, mask, Wq, bq, Wk, bk, Wv, bv, Wo, bo.
// ---------------------------------------------------------------------------
extern "C" void kernel_launch(void* const* d_in, const int* in_sizes, int n_in,
                              void* d_out, int out_size)
{
    const float* Q  = (const float*)d_in[0];
    const float* K  = (const float*)d_in[1];
    const float* V  = (const float*)d_in[2];
    const float* Wq = (const float*)d_in[4];
    const float* bq = (const float*)d_in[5];
    const float* Wk = (const float*)d_in[6];
    const float* bk = (const float*)d_in[7];
    const float* Wv = (const float*)d_in[8];
    const float* bv = (const float*)d_in[9];
    const float* Wo = (const float*)d_in[10];
    const float* bo = (const float*)d_in[11];
    float* out = (float*)d_out;

    cudaFuncSetAttribute(attn_kernel,
                         cudaFuncAttributeMaxDynamicSharedMemorySize, (int)ATTN_SMEM);
    cudaFuncSetAttribute(qkv_wmma_kernel,
                         cudaFuncAttributeMaxDynamicSharedMemorySize, SMEM_GEMM_BYTES);
    cudaFuncSetAttribute(out_wmma_kernel,
                         cudaFuncAttributeMaxDynamicSharedMemorySize, SMEM_GEMM_BYTES);

    const int nI4 = MMR * DDM / 4;   // 1048576
    const int nW4 = DDM * DDM / 4;   // 262144

    cvt_kernel<<<nI4 / 256, 256>>>(Q,  0, nI4);
    cvt_kernel<<<nI4 / 256, 256>>>(K,  1, nI4);
    cvt_kernel<<<nI4 / 256, 256>>>(V,  2, nI4);
    cvt_kernel<<<nW4 / 256, 256>>>(Wq, 3, nW4);
    cvt_kernel<<<nW4 / 256, 256>>>(Wk, 4, nW4);
    cvt_kernel<<<nW4 / 256, 256>>>(Wv, 5, nW4);
    cvt_kernel<<<nW4 / 256, 256>>>(Wo, 6, nW4);

    dim3 gqkv(DDM / 128, MMR / 128, 3);
    qkv_wmma_kernel<<<gqkv, 256, SMEM_GEMM_BYTES>>>(bq, bk, bv);

    dim3 gattn(LL / 64, BB * HH);
    attn_kernel<<<gattn, 256, ATTN_SMEM>>>();

    cvt_kernel<<<nI4 / 256, 256>>>(nullptr, 7, nI4);

    dim3 gout(DDM / 128, MMR / 128);
    out_wmma_kernel<<<gout, 256, SMEM_GEMM_BYTES>>>(bo, out);
}

// round 4
// speedup vs baseline: 1.9593x; 1.4852x over previous
#include <cuda_runtime.h>
#include <cuda_fp16.h>
#include <mma.h>
#include <math.h>
#include <stdint.h>

using namespace nvcuda;

// Problem constants
#define BB  2
#define LL  2048
#define DDM 1024
#define HH  16
#define DKK 64
#define MMR (BB * LL)      // 4096 rows

// ---------------- scratch (device globals; no allocation allowed) ----------
// fp16 hi/lo split buffers (inputs + weights)
__device__ __half g_qh[(size_t)MMR * DDM], g_ql[(size_t)MMR * DDM];
__device__ __half g_kh[(size_t)MMR * DDM], g_kl[(size_t)MMR * DDM];
__device__ __half g_vh[(size_t)MMR * DDM], g_vl[(size_t)MMR * DDM];
__device__ __half g_wqh[(size_t)DDM * DDM], g_wql[(size_t)DDM * DDM];
__device__ __half g_wkh[(size_t)DDM * DDM], g_wkl[(size_t)DDM * DDM];
__device__ __half g_wvh[(size_t)DDM * DDM], g_wvl[(size_t)DDM * DDM];
__device__ __half g_woh[(size_t)DDM * DDM], g_wol[(size_t)DDM * DDM];
// projected q/k/v (hi/lo), attention output (hi/lo)
__device__ __half g_pqh[(size_t)MMR * DDM], g_pql[(size_t)MMR * DDM];
__device__ __half g_pkh[(size_t)MMR * DDM], g_pkl[(size_t)MMR * DDM];
__device__ __half g_pvh[(size_t)MMR * DDM], g_pvl[(size_t)MMR * DDM];
__device__ __half g_ah[(size_t)MMR * DDM],  g_al[(size_t)MMR * DDM];

// ---------------- fp32 -> fp16 hi/lo split conversion ----------------------
// which: 0..2 -> Q,K,V inputs; 3..6 -> Wq,Wk,Wv,Wo
__global__ __launch_bounds__(256) void cvt_kernel(const float* __restrict__ x,
                                                  int which, int n4)
{
    __half *hi, *lo;
    switch (which) {
        case 0: hi = g_qh;  lo = g_ql;  break;
        case 1: hi = g_kh;  lo = g_kl;  break;
        case 2: hi = g_vh;  lo = g_vl;  break;
        case 3: hi = g_wqh; lo = g_wql; break;
        case 4: hi = g_wkh; lo = g_wkl; break;
        case 5: hi = g_wvh; lo = g_wvl; break;
        default: hi = g_woh; lo = g_wol; break;
    }
    int i = blockIdx.x * blockDim.x + threadIdx.x;
    if (i >= n4) return;
    float4 v = ((const float4*)x)[i];
    __half h0 = __float2half(v.x);
    __half h1 = __float2half(v.y);
    __half h2 = __float2half(v.z);
    __half h3 = __float2half(v.w);
    __half l0 = __float2half(v.x - __half2float(h0));
    __half l1 = __float2half(v.y - __half2float(h1));
    __half l2 = __float2half(v.z - __half2float(h2));
    __half l3 = __float2half(v.w - __half2float(h3));
    __half2* hp = (__half2*)hi;
    __half2* lp = (__half2*)lo;
    hp[i * 2 + 0] = __halves2half2(h0, h1);
    hp[i * 2 + 1] = __halves2half2(h2, h3);
    lp[i * 2 + 0] = __halves2half2(l0, l1);
    lp[i * 2 + 1] = __halves2half2(l2, l3);
}

// ---------------- WMMA GEMM: C = (Ah+Al)(Wh+Wl)^T + bias -------------------
// CTA tile 128x128, 8 warps (4x2), each warp 32x64.  K chunks of 64.
// HALF_OUT: write hi/lo fp16 pair instead of fp32.
#define LDHW 72
#define A_TILE (128 * LDHW)
#define SMEM_GEMM_BYTES (4 * A_TILE * 2)

template<bool HALF_OUT>
__device__ __forceinline__ void wmma_gemm(
    const __half* __restrict__ Ah, const __half* __restrict__ Al,
    const __half* __restrict__ Wh, const __half* __restrict__ Wl,
    const float* __restrict__ bias, float* __restrict__ Cf,
    __half* __restrict__ Ch, __half* __restrict__ Cl)
{
    extern __shared__ char smem[];
    __half* sAh = (__half*)smem;
    __half* sAl = sAh + A_TILE;
    __half* sWh = sAl + A_TILE;
    __half* sWl = sWh + A_TILE;

    const int tid  = threadIdx.x;
    const int w    = tid >> 5, lane = tid & 31;
    const int wm   = w & 3, wn = w >> 2;
    const int m0   = blockIdx.y * 128;
    const int n0   = blockIdx.x * 128;

    wmma::fragment<wmma::accumulator, 16, 16, 16, float> acc[2][4];
#pragma unroll
    for (int i = 0; i < 2; i++)
#pragma unroll
        for (int j = 0; j < 4; j++) wmma::fill_fragment(acc[i][j], 0.0f);

    const __half* srcs[4] = {Ah, Al, Wh, Wl};
    __half* dsts[4] = {sAh, sAl, sWh, sWl};

    for (int c = 0; c < 16; c++) {
        const int k0 = c * 64;
        float4 buf[16];
#pragma unroll
        for (int t = 0; t < 4; t++) {
            const __half* src = srcs[t];
            const int rb = (t < 2) ? m0 : n0;
#pragma unroll
            for (int i = 0; i < 4; i++) {
                int id = i * 256 + tid;
                int r = id >> 3, q = id & 7;
                buf[t * 4 + i] =
                    *(const float4*)&src[(size_t)(rb + r) * DDM + k0 + q * 8];
            }
        }
        __syncthreads();
#pragma unroll
        for (int t = 0; t < 4; t++) {
#pragma unroll
            for (int i = 0; i < 4; i++) {
                int id = i * 256 + tid;
                int r = id >> 3, q = id & 7;
                *(float4*)&dsts[t][r * LDHW + q * 8] = buf[t * 4 + i];
            }
        }
        __syncthreads();

#pragma unroll
        for (int kk = 0; kk < 4; kk++) {
            wmma::fragment<wmma::matrix_a, 16, 16, 16, __half, wmma::row_major> a_h[2], a_l[2];
#pragma unroll
            for (int i = 0; i < 2; i++) {
                const int ro = (wm * 32 + i * 16) * LDHW + kk * 16;
                wmma::load_matrix_sync(a_h[i], sAh + ro, LDHW);
                wmma::load_matrix_sync(a_l[i], sAl + ro, LDHW);
            }
#pragma unroll
            for (int j = 0; j < 4; j++) {
                wmma::fragment<wmma::matrix_b, 16, 16, 16, __half, wmma::col_major> b_h, b_l;
                const int co = (wn * 64 + j * 16) * LDHW + kk * 16;
                wmma::load_matrix_sync(b_h, sWh + co, LDHW);
                wmma::load_matrix_sync(b_l, sWl + co, LDHW);
#pragma unroll
                for (int i = 0; i < 2; i++) {
                    wmma::mma_sync(acc[i][j], a_h[i], b_h, acc[i][j]);
                    wmma::mma_sync(acc[i][j], a_h[i], b_l, acc[i][j]);
                    wmma::mma_sync(acc[i][j], a_l[i], b_h, acc[i][j]);
                }
            }
        }
    }

    __syncthreads();
    float* stage = (float*)smem + w * (32 * 68);
#pragma unroll
    for (int i = 0; i < 2; i++)
#pragma unroll
        for (int j = 0; j < 4; j++)
            wmma::store_matrix_sync(stage + i * 16 * 68 + j * 16, acc[i][j],
                                    68, wmma::mem_row_major);
    __syncwarp();

    const int col4 = (lane & 15) * 4;
    const int rb   = lane >> 4;
    const int ng   = n0 + wn * 64 + col4;
    float4 b4 = *(const float4*)&bias[ng];
#pragma unroll
    for (int r = 0; r < 16; r++) {
        int row = rb + r * 2;
        float4 v = *(float4*)&stage[row * 68 + col4];
        v.x += b4.x; v.y += b4.y; v.z += b4.z; v.w += b4.w;
        size_t off = (size_t)(m0 + wm * 32 + row) * DDM + ng;
        if (HALF_OUT) {
            __half hh[4], ll[4];
            hh[0] = __float2half(v.x); ll[0] = __float2half(v.x - __half2float(hh[0]));
            hh[1] = __float2half(v.y); ll[1] = __float2half(v.y - __half2float(hh[1]));
            hh[2] = __float2half(v.z); ll[2] = __float2half(v.z - __half2float(hh[2]));
            hh[3] = __float2half(v.w); ll[3] = __float2half(v.w - __half2float(hh[3]));
            *(uint2*)&Ch[off] = *(uint2*)hh;
            *(uint2*)&Cl[off] = *(uint2*)ll;
        } else {
            *(float4*)&Cf[off] = v;
        }
    }
}

__global__ __launch_bounds__(256) void qkv_wmma_kernel(
    const float* __restrict__ bq, const float* __restrict__ bk,
    const float* __restrict__ bv)
{
    if (blockIdx.z == 0)
        wmma_gemm<true>(g_qh, g_ql, g_wqh, g_wql, bq, nullptr, g_pqh, g_pql);
    else if (blockIdx.z == 1)
        wmma_gemm<true>(g_kh, g_kl, g_wkh, g_wkl, bk, nullptr, g_pkh, g_pkl);
    else
        wmma_gemm<true>(g_vh, g_vl, g_wvh, g_wvl, bv, nullptr, g_pvh, g_pvl);
}

__global__ __launch_bounds__(256) void out_wmma_kernel(
    const float* __restrict__ bo, float* __restrict__ out)
{
    wmma_gemm<false>(g_ah, g_al, g_woh, g_wol, bo, out, nullptr, nullptr);
}

// ---------------------------------------------------------------------------
// WMMA flash attention (causal). CTA = 64 q-rows of one (b,h).
// 8 warps in 4x2 grid (wm: 16-row stripe, wn: 32-col stripe).
// S = QK^T via 3 hi/lo mma combos -> fp32 smem; softmax in smem (4 thr/row);
// P hi/lo -> smem; O in fp32 smem, rescaled and accumulated via WMMA.
// ---------------------------------------------------------------------------
#define ALD 72  // half-tile leading dim
#define FLD 72  // float-tile leading dim
#define ATTN_SMEM_BYTES (8 * 64 * ALD * 2 + 2 * 64 * FLD * 4 + 2 * 64 * 4)

__global__ __launch_bounds__(256) void attn_wmma_kernel()
{
    extern __shared__ char smraw[];
    __half* sQh = (__half*)smraw;
    __half* sQl = sQh + 64 * ALD;
    __half* sKh = sQl + 64 * ALD;
    __half* sKl = sKh + 64 * ALD;
    __half* sVh = sKl + 64 * ALD;
    __half* sVl = sVh + 64 * ALD;
    __half* sPh = sVl + 64 * ALD;
    __half* sPl = sPh + 64 * ALD;
    float*  sS  = (float*)(sPl + 64 * ALD);
    float*  sO  = sS + 64 * FLD;
    float*  sM  = sO + 64 * FLD;
    float*  sL  = sM + 64;

    const int tid  = threadIdx.x;
    const int w    = tid >> 5;
    const int wm   = w & 3, wn = w >> 2;
    const int qt   = gridDim.x - 1 - blockIdx.x;   // big tiles first
    const int bh   = blockIdx.y;
    const int b    = bh >> 4, h = bh & 15;
    const int qbase = qt * 64;

    const size_t headoff = (size_t)b * LL * DDM + (size_t)h * DKK;
    const __half* qhg = g_pqh + headoff;
    const __half* qlg = g_pql + headoff;
    const __half* khg = g_pkh + headoff;
    const __half* klg = g_pkl + headoff;
    const __half* vhg = g_pvh + headoff;
    const __half* vlg = g_pvl + headoff;

    // Load Q tile (64x64 hi + lo)
#pragma unroll
    for (int p = 0; p < 2; p++) {
        int id = p * 256 + tid;
        int r = id >> 3, c8 = (id & 7) * 8;
        *(float4*)&sQh[r * ALD + c8] = *(const float4*)&qhg[(size_t)(qbase + r) * DDM + c8];
        *(float4*)&sQl[r * ALD + c8] = *(const float4*)&qlg[(size_t)(qbase + r) * DDM + c8];
    }
    // Init O, m, l
    {
        int row = tid >> 2, q = tid & 3;
        float4 z = make_float4(0.f, 0.f, 0.f, 0.f);
#pragma unroll
        for (int i = 0; i < 4; i++)
            *(float4*)&sO[row * FLD + q * 16 + i * 4] = z;
    }
    if (tid < 64) { sM[tid] = -INFINITY; sL[tid] = 0.f; }
    __syncthreads();

    for (int kt = 0; kt <= qt; kt++) {
        const int kbase = kt * 64;

        // Load K, V (hi + lo)
#pragma unroll
        for (int p = 0; p < 2; p++) {
            int id = p * 256 + tid;
            int r = id >> 3, c8 = (id & 7) * 8;
            size_t go = (size_t)(kbase + r) * DDM + c8;
            *(float4*)&sKh[r * ALD + c8] = *(const float4*)&khg[go];
            *(float4*)&sKl[r * ALD + c8] = *(const float4*)&klg[go];
            *(float4*)&sVh[r * ALD + c8] = *(const float4*)&vhg[go];
            *(float4*)&sVl[r * ALD + c8] = *(const float4*)&vlg[go];
        }
        __syncthreads();

        // S = Q K^T  (warp: rows wm*16, cols wn*32)
        {
            wmma::fragment<wmma::accumulator, 16, 16, 16, float> s_acc[2];
            wmma::fill_fragment(s_acc[0], 0.0f);
            wmma::fill_fragment(s_acc[1], 0.0f);
#pragma unroll
            for (int kk = 0; kk < 4; kk++) {
                wmma::fragment<wmma::matrix_a, 16, 16, 16, __half, wmma::row_major> a_h, a_l;
                wmma::load_matrix_sync(a_h, sQh + (wm * 16) * ALD + kk * 16, ALD);
                wmma::load_matrix_sync(a_l, sQl + (wm * 16) * ALD + kk * 16, ALD);
#pragma unroll
                for (int j = 0; j < 2; j++) {
                    wmma::fragment<wmma::matrix_b, 16, 16, 16, __half, wmma::col_major> b_h, b_l;
                    const int co = (wn * 32 + j * 16) * ALD + kk * 16;
                    wmma::load_matrix_sync(b_h, sKh + co, ALD);
                    wmma::load_matrix_sync(b_l, sKl + co, ALD);
                    wmma::mma_sync(s_acc[j], a_h, b_h, s_acc[j]);
                    wmma::mma_sync(s_acc[j], a_h, b_l, s_acc[j]);
                    wmma::mma_sync(s_acc[j], a_l, b_h, s_acc[j]);
                }
            }
#pragma unroll
            for (int j = 0; j < 2; j++)
                wmma::store_matrix_sync(sS + (wm * 16) * FLD + wn * 32 + j * 16,
                                        s_acc[j], FLD, wmma::mem_row_major);
        }
        __syncthreads();

        // Softmax (4 threads per row, 16 cols each)
        {
            const int row = tid >> 2, q = tid & 3;
            float vals[16];
#pragma unroll
            for (int i = 0; i < 4; i++) {
                float4 v4 = *(float4*)&sS[row * FLD + q * 16 + i * 4];
                vals[i * 4 + 0] = v4.x; vals[i * 4 + 1] = v4.y;
                vals[i * 4 + 2] = v4.z; vals[i * 4 + 3] = v4.w;
            }
#pragma unroll
            for (int i = 0; i < 16; i++) vals[i] *= 0.125f;
            if (kt == qt) {
#pragma unroll
                for (int i = 0; i < 16; i++)
                    if (q * 16 + i > row) vals[i] = -INFINITY;
            }
            float mx = vals[0];
#pragma unroll
            for (int i = 1; i < 16; i++) mx = fmaxf(mx, vals[i]);
            mx = fmaxf(mx, __shfl_xor_sync(0xffffffffu, mx, 1));
            mx = fmaxf(mx, __shfl_xor_sync(0xffffffffu, mx, 2));
            const float mold = sM[row];
            const float mnew = fmaxf(mold, mx);
            float sum = 0.f;
            __half ph[16], pl[16];
#pragma unroll
            for (int i = 0; i < 16; i++) {
                float p = __expf(vals[i] - mnew);
                sum += p;
                ph[i] = __float2half(p);
                pl[i] = __float2half(p - __half2float(ph[i]));
            }
            sum += __shfl_xor_sync(0xffffffffu, sum, 1);
            sum += __shfl_xor_sync(0xffffffffu, sum, 2);
            const float alpha = __expf(mold - mnew);
            // rescale O (same 16 cols this thread owns)
#pragma unroll
            for (int i = 0; i < 4; i++) {
                float4 o4 = *(float4*)&sO[row * FLD + q * 16 + i * 4];
                o4.x *= alpha; o4.y *= alpha; o4.z *= alpha; o4.w *= alpha;
                *(float4*)&sO[row * FLD + q * 16 + i * 4] = o4;
            }
            *(float4*)&sPh[row * ALD + q * 16 + 0] = *(float4*)&ph[0];
            *(float4*)&sPh[row * ALD + q * 16 + 8] = *(float4*)&ph[8];
            *(float4*)&sPl[row * ALD + q * 16 + 0] = *(float4*)&pl[0];
            *(float4*)&sPl[row * ALD + q * 16 + 8] = *(float4*)&pl[8];
            if (q == 0) {
                sL[row] = sL[row] * alpha + sum;
                sM[row] = mnew;
            }
        }
        __syncthreads();

        // O += P V
        {
            wmma::fragment<wmma::accumulator, 16, 16, 16, float> o_acc[2];
#pragma unroll
            for (int j = 0; j < 2; j++)
                wmma::load_matrix_sync(o_acc[j],
                                       sO + (wm * 16) * FLD + wn * 32 + j * 16,
                                       FLD, wmma::mem_row_major);
#pragma unroll
            for (int kk = 0; kk < 4; kk++) {
                wmma::fragment<wmma::matrix_a, 16, 16, 16, __half, wmma::row_major> a_h, a_l;
                wmma::load_matrix_sync(a_h, sPh + (wm * 16) * ALD + kk * 16, ALD);
                wmma::load_matrix_sync(a_l, sPl + (wm * 16) * ALD + kk * 16, ALD);
#pragma unroll
                for (int j = 0; j < 2; j++) {
                    wmma::fragment<wmma::matrix_b, 16, 16, 16, __half, wmma::row_major> b_h, b_l;
                    const int vo = (kk * 16) * ALD + wn * 32 + j * 16;
                    wmma::load_matrix_sync(b_h, sVh + vo, ALD);
                    wmma::load_matrix_sync(b_l, sVl + vo, ALD);
                    wmma::mma_sync(o_acc[j], a_h, b_h, o_acc[j]);
                    wmma::mma_sync(o_acc[j], a_h, b_l, o_acc[j]);
                    wmma::mma_sync(o_acc[j], a_l, b_h, o_acc[j]);
                }
            }
#pragma unroll
            for (int j = 0; j < 2; j++)
                wmma::store_matrix_sync(sO + (wm * 16) * FLD + wn * 32 + j * 16,
                                        o_acc[j], FLD, wmma::mem_row_major);
        }
        __syncthreads();
    }

    // Epilogue: normalize and write hi/lo fp16 O
    {
        const int row = tid >> 2, q = tid & 3;
        const float inv = 1.0f / sL[row];
        __half hh[16], ll[16];
#pragma unroll
        for (int i = 0; i < 4; i++) {
            float4 o4 = *(float4*)&sO[row * FLD + q * 16 + i * 4];
            float vv[4] = {o4.x * inv, o4.y * inv, o4.z * inv, o4.w * inv};
#pragma unroll
            for (int u = 0; u < 4; u++) {
                hh[i * 4 + u] = __float2half(vv[u]);
                ll[i * 4 + u] = __float2half(vv[u] - __half2float(hh[i * 4 + u]));
            }
        }
        size_t off = (size_t)(b * LL + qbase + row) * DDM + h * DKK + q * 16;
        *(float4*)&g_ah[off + 0] = *(float4*)&hh[0];
        *(float4*)&g_ah[off + 8] = *(float4*)&hh[8];
        *(float4*)&g_al[off + 0] = *(float4*)&ll[0];
        *(float4*)&g_al[off + 8] = *(float4*)&ll[8];
    }
}

// ---------------------------------------------------------------------------
// Inputs (metadata order): Q, K, V, mask, Wq, bq, Wk, bk, Wv, bv, Wo, bo.
// ---------------------------------------------------------------------------
extern "C" void kernel_launch(void* const* d_in, const int* in_sizes, int n_in,
                              void* d_out, int out_size)
{
    const float* Q  = (const float*)d_in[0];
    const float* K  = (const float*)d_in[1];
    const float* V  = (const float*)d_in[2];
    const float* Wq = (const float*)d_in[4];
    const float* bq = (const float*)d_in[5];
    const float* Wk = (const float*)d_in[6];
    const float* bk = (const float*)d_in[7];
    const float* Wv = (const float*)d_in[8];
    const float* bv = (const float*)d_in[9];
    const float* Wo = (const float*)d_in[10];
    const float* bo = (const float*)d_in[11];
    float* out = (float*)d_out;

    cudaFuncSetAttribute(qkv_wmma_kernel,
                         cudaFuncAttributeMaxDynamicSharedMemorySize, SMEM_GEMM_BYTES);
    cudaFuncSetAttribute(out_wmma_kernel,
                         cudaFuncAttributeMaxDynamicSharedMemorySize, SMEM_GEMM_BYTES);
    cudaFuncSetAttribute(attn_wmma_kernel,
                         cudaFuncAttributeMaxDynamicSharedMemorySize, ATTN_SMEM_BYTES);

    const int nI4 = MMR * DDM / 4;
    const int nW4 = DDM * DDM / 4;

    cvt_kernel<<<nI4 / 256, 256>>>(Q,  0, nI4);
    cvt_kernel<<<nI4 / 256, 256>>>(K,  1, nI4);
    cvt_kernel<<<nI4 / 256, 256>>>(V,  2, nI4);
    cvt_kernel<<<nW4 / 256, 256>>>(Wq, 3, nW4);
    cvt_kernel<<<nW4 / 256, 256>>>(Wk, 4, nW4);
    cvt_kernel<<<nW4 / 256, 256>>>(Wv, 5, nW4);
    cvt_kernel<<<nW4 / 256, 256>>>(Wo, 6, nW4);

    dim3 gqkv(DDM / 128, MMR / 128, 3);
    qkv_wmma_kernel<<<gqkv, 256, SMEM_GEMM_BYTES>>>(bq, bk, bv);

    dim3 gattn(LL / 64, BB * HH);
    attn_wmma_kernel<<<gattn, 256, ATTN_SMEM_BYTES>>>();

    dim3 gout(DDM / 128, MMR / 128);
    out_wmma_kernel<<<gout, 256, SMEM_GEMM_BYTES>>>(bo, out);
}

// round 5
// speedup vs baseline: 2.0060x; 1.0238x over previous
#include <cuda_runtime.h>
#include <cuda_fp16.h>
#include <mma.h>
#include <math.h>
#include <stdint.h>

using namespace nvcuda;

// Problem constants
#define BB  2
#define LL  2048
#define DDM 1024
#define HH  16
#define DKK 64
#define MMR (BB * LL)      // 4096 rows

// ---------------- scratch (device globals; no allocation allowed) ----------
// weight hi/lo split buffers
__device__ __half g_wqh[(size_t)DDM * DDM], g_wql[(size_t)DDM * DDM];
__device__ __half g_wkh[(size_t)DDM * DDM], g_wkl[(size_t)DDM * DDM];
__device__ __half g_wvh[(size_t)DDM * DDM], g_wvl[(size_t)DDM * DDM];
__device__ __half g_woh[(size_t)DDM * DDM], g_wol[(size_t)DDM * DDM];
// projected q/k/v (hi/lo), attention output (hi/lo)
__device__ __half g_pqh[(size_t)MMR * DDM], g_pql[(size_t)MMR * DDM];
__device__ __half g_pkh[(size_t)MMR * DDM], g_pkl[(size_t)MMR * DDM];
__device__ __half g_pvh[(size_t)MMR * DDM], g_pvl[(size_t)MMR * DDM];
__device__ __half g_ah[(size_t)MMR * DDM],  g_al[(size_t)MMR * DDM];

// ---------------- fp32 -> fp16 hi/lo split (weights only) -------------------
__global__ __launch_bounds__(256) void cvt_kernel(const float* __restrict__ x,
                                                  int which, int n4)
{
    __half *hi, *lo;
    switch (which) {
        case 0: hi = g_wqh; lo = g_wql; break;
        case 1: hi = g_wkh; lo = g_wkl; break;
        case 2: hi = g_wvh; lo = g_wvl; break;
        default: hi = g_woh; lo = g_wol; break;
    }
    int i = blockIdx.x * blockDim.x + threadIdx.x;
    if (i >= n4) return;
    float4 v = ((const float4*)x)[i];
    __half h0 = __float2half(v.x);
    __half h1 = __float2half(v.y);
    __half h2 = __float2half(v.z);
    __half h3 = __float2half(v.w);
    __half l0 = __float2half(v.x - __half2float(h0));
    __half l1 = __float2half(v.y - __half2float(h1));
    __half l2 = __float2half(v.z - __half2float(h2));
    __half l3 = __float2half(v.w - __half2float(h3));
    __half2* hp = (__half2*)hi;
    __half2* lp = (__half2*)lo;
    hp[i * 2 + 0] = __halves2half2(h0, h1);
    hp[i * 2 + 1] = __halves2half2(h2, h3);
    lp[i * 2 + 0] = __halves2half2(l0, l1);
    lp[i * 2 + 1] = __halves2half2(l2, l3);
}

// ---------------- WMMA GEMM: C = (Ah+Al)(Wh+Wl)^T + bias -------------------
// CTA tile 128x128, 8 warps (4x2), each warp 32x64.  K chunks of 64.
// A_FP32: read A as fp32 and split to hi/lo during smem staging (same bytes).
// HALF_OUT: write hi/lo fp16 pair instead of fp32.
#define LDHW 72
#define A_TILE (128 * LDHW)
#define SMEM_GEMM_BYTES (4 * A_TILE * 2)

__device__ __forceinline__ void split8(const float4& a, const float4& b,
                                       __half* hh, __half* ll)
{
    float v[8] = {a.x, a.y, a.z, a.w, b.x, b.y, b.z, b.w};
#pragma unroll
    for (int u = 0; u < 8; u++) {
        hh[u] = __float2half(v[u]);
        ll[u] = __float2half(v[u] - __half2float(hh[u]));
    }
}

template<bool A_FP32, bool HALF_OUT>
__device__ __forceinline__ void wmma_gemm(
    const float* __restrict__ Af,
    const __half* __restrict__ Ah, const __half* __restrict__ Al,
    const __half* __restrict__ Wh, const __half* __restrict__ Wl,
    const float* __restrict__ bias, float* __restrict__ Cf,
    __half* __restrict__ Ch, __half* __restrict__ Cl)
{
    extern __shared__ char smem[];
    __half* sAh = (__half*)smem;
    __half* sAl = sAh + A_TILE;
    __half* sWh = sAl + A_TILE;
    __half* sWl = sWh + A_TILE;

    const int tid  = threadIdx.x;
    const int w    = tid >> 5, lane = tid & 31;
    const int wm   = w & 3, wn = w >> 2;
    const int m0   = blockIdx.y * 128;
    const int n0   = blockIdx.x * 128;

    wmma::fragment<wmma::accumulator, 16, 16, 16, float> acc[2][4];
#pragma unroll
    for (int i = 0; i < 2; i++)
#pragma unroll
        for (int j = 0; j < 4; j++) wmma::fill_fragment(acc[i][j], 0.0f);

    for (int c = 0; c < 16; c++) {
        const int k0 = c * 64;
        float4 abuf[8];
        float4 wbuf[8];
        if (A_FP32) {
#pragma unroll
            for (int i = 0; i < 4; i++) {
                int id = i * 256 + tid;
                int r = id >> 3, q = id & 7;
                const float* ap = &Af[(size_t)(m0 + r) * DDM + k0 + q * 8];
                abuf[i * 2 + 0] = *(const float4*)ap;
                abuf[i * 2 + 1] = *(const float4*)(ap + 4);
            }
        } else {
#pragma unroll
            for (int i = 0; i < 4; i++) {
                int id = i * 256 + tid;
                int r = id >> 3, q = id & 7;
                abuf[i]     = *(const float4*)&Ah[(size_t)(m0 + r) * DDM + k0 + q * 8];
                abuf[4 + i] = *(const float4*)&Al[(size_t)(m0 + r) * DDM + k0 + q * 8];
            }
        }
#pragma unroll
        for (int i = 0; i < 4; i++) {
            int id = i * 256 + tid;
            int r = id >> 3, q = id & 7;
            wbuf[i]     = *(const float4*)&Wh[(size_t)(n0 + r) * DDM + k0 + q * 8];
            wbuf[4 + i] = *(const float4*)&Wl[(size_t)(n0 + r) * DDM + k0 + q * 8];
        }
        __syncthreads();   // previous chunk's compute done
        if (A_FP32) {
#pragma unroll
            for (int i = 0; i < 4; i++) {
                int id = i * 256 + tid;
                int r = id >> 3, q = id & 7;
                __half hh[8], ll[8];
                split8(abuf[i * 2 + 0], abuf[i * 2 + 1], hh, ll);
                *(float4*)&sAh[r * LDHW + q * 8] = *(float4*)hh;
                *(float4*)&sAl[r * LDHW + q * 8] = *(float4*)ll;
            }
        } else {
#pragma unroll
            for (int i = 0; i < 4; i++) {
                int id = i * 256 + tid;
                int r = id >> 3, q = id & 7;
                *(float4*)&sAh[r * LDHW + q * 8] = abuf[i];
                *(float4*)&sAl[r * LDHW + q * 8] = abuf[4 + i];
            }
        }
#pragma unroll
        for (int i = 0; i < 4; i++) {
            int id = i * 256 + tid;
            int r = id >> 3, q = id & 7;
            *(float4*)&sWh[r * LDHW + q * 8] = wbuf[i];
            *(float4*)&sWl[r * LDHW + q * 8] = wbuf[4 + i];
        }
        __syncthreads();

#pragma unroll
        for (int kk = 0; kk < 4; kk++) {
            wmma::fragment<wmma::matrix_a, 16, 16, 16, __half, wmma::row_major> a_h[2], a_l[2];
#pragma unroll
            for (int i = 0; i < 2; i++) {
                const int ro = (wm * 32 + i * 16) * LDHW + kk * 16;
                wmma::load_matrix_sync(a_h[i], sAh + ro, LDHW);
                wmma::load_matrix_sync(a_l[i], sAl + ro, LDHW);
            }
#pragma unroll
            for (int j = 0; j < 4; j++) {
                wmma::fragment<wmma::matrix_b, 16, 16, 16, __half, wmma::col_major> b_h, b_l;
                const int co = (wn * 64 + j * 16) * LDHW + kk * 16;
                wmma::load_matrix_sync(b_h, sWh + co, LDHW);
                wmma::load_matrix_sync(b_l, sWl + co, LDHW);
#pragma unroll
                for (int i = 0; i < 2; i++) {
                    wmma::mma_sync(acc[i][j], a_h[i], b_h, acc[i][j]);
                    wmma::mma_sync(acc[i][j], a_h[i], b_l, acc[i][j]);
                    wmma::mma_sync(acc[i][j], a_l[i], b_h, acc[i][j]);
                }
            }
        }
    }

    __syncthreads();
    float* stage = (float*)smem + w * (32 * 68);
#pragma unroll
    for (int i = 0; i < 2; i++)
#pragma unroll
        for (int j = 0; j < 4; j++)
            wmma::store_matrix_sync(stage + i * 16 * 68 + j * 16, acc[i][j],
                                    68, wmma::mem_row_major);
    __syncwarp();

    const int col4 = (lane & 15) * 4;
    const int rb   = lane >> 4;
    const int ng   = n0 + wn * 64 + col4;
    float4 b4 = *(const float4*)&bias[ng];
#pragma unroll
    for (int r = 0; r < 16; r++) {
        int row = rb + r * 2;
        float4 v = *(float4*)&stage[row * 68 + col4];
        v.x += b4.x; v.y += b4.y; v.z += b4.z; v.w += b4.w;
        size_t off = (size_t)(m0 + wm * 32 + row) * DDM + ng;
        if (HALF_OUT) {
            __half hh[4], ll[4];
            hh[0] = __float2half(v.x); ll[0] = __float2half(v.x - __half2float(hh[0]));
            hh[1] = __float2half(v.y); ll[1] = __float2half(v.y - __half2float(hh[1]));
            hh[2] = __float2half(v.z); ll[2] = __float2half(v.z - __half2float(hh[2]));
            hh[3] = __float2half(v.w); ll[3] = __float2half(v.w - __half2float(hh[3]));
            *(uint2*)&Ch[off] = *(uint2*)hh;
            *(uint2*)&Cl[off] = *(uint2*)ll;
        } else {
            *(float4*)&Cf[off] = v;
        }
    }
}

__global__ __launch_bounds__(256) void qkv_wmma_kernel(
    const float* __restrict__ Q, const float* __restrict__ K,
    const float* __restrict__ V,
    const float* __restrict__ bq, const float* __restrict__ bk,
    const float* __restrict__ bv)
{
    if (blockIdx.z == 0)
        wmma_gemm<true, true>(Q, nullptr, nullptr, g_wqh, g_wql, bq,
                              nullptr, g_pqh, g_pql);
    else if (blockIdx.z == 1)
        wmma_gemm<true, true>(K, nullptr, nullptr, g_wkh, g_wkl, bk,
                              nullptr, g_pkh, g_pkl);
    else
        wmma_gemm<true, true>(V, nullptr, nullptr, g_wvh, g_wvl, bv,
                              nullptr, g_pvh, g_pvl);
}

__global__ __launch_bounds__(256) void out_wmma_kernel(
    const float* __restrict__ bo, float* __restrict__ out)
{
    wmma_gemm<false, false>(nullptr, g_ah, g_al, g_woh, g_wol, bo,
                            out, nullptr, nullptr);
}

// ---------------------------------------------------------------------------
// WMMA flash attention (causal). CTA = 64 q-rows of one (b,h).
// 8 warps in 4x2 grid.  S via 3 hi/lo mma combos -> fp32 smem; softmax in
// smem (4 thr/row); P hi/lo -> smem; O in fp32 smem, WMMA-accumulated.
// ---------------------------------------------------------------------------
#define ALD 72
#define FLD 72
#define ATTN_SMEM_BYTES (8 * 64 * ALD * 2 + 2 * 64 * FLD * 4 + 2 * 64 * 4)

__global__ __launch_bounds__(256) void attn_wmma_kernel()
{
    extern __shared__ char smraw[];
    __half* sQh = (__half*)smraw;
    __half* sQl = sQh + 64 * ALD;
    __half* sKh = sQl + 64 * ALD;
    __half* sKl = sKh + 64 * ALD;
    __half* sVh = sKl + 64 * ALD;
    __half* sVl = sVh + 64 * ALD;
    __half* sPh = sVl + 64 * ALD;
    __half* sPl = sPh + 64 * ALD;
    float*  sS  = (float*)(sPl + 64 * ALD);
    float*  sO  = sS + 64 * FLD;
    float*  sM  = sO + 64 * FLD;
    float*  sL  = sM + 64;

    const int tid  = threadIdx.x;
    const int w    = tid >> 5;
    const int wm   = w & 3, wn = w >> 2;
    const int qt   = gridDim.x - 1 - blockIdx.x;
    const int bh   = blockIdx.y;
    const int b    = bh >> 4, h = bh & 15;
    const int qbase = qt * 64;

    const size_t headoff = (size_t)b * LL * DDM + (size_t)h * DKK;
    const __half* qhg = g_pqh + headoff;
    const __half* qlg = g_pql + headoff;
    const __half* khg = g_pkh + headoff;
    const __half* klg = g_pkl + headoff;
    const __half* vhg = g_pvh + headoff;
    const __half* vlg = g_pvl + headoff;

#pragma unroll
    for (int p = 0; p < 2; p++) {
        int id = p * 256 + tid;
        int r = id >> 3, c8 = (id & 7) * 8;
        *(float4*)&sQh[r * ALD + c8] = *(const float4*)&qhg[(size_t)(qbase + r) * DDM + c8];
        *(float4*)&sQl[r * ALD + c8] = *(const float4*)&qlg[(size_t)(qbase + r) * DDM + c8];
    }
    {
        int row = tid >> 2, q = tid & 3;
        float4 z = make_float4(0.f, 0.f, 0.f, 0.f);
#pragma unroll
        for (int i = 0; i < 4; i++)
            *(float4*)&sO[row * FLD + q * 16 + i * 4] = z;
    }
    if (tid < 64) { sM[tid] = -INFINITY; sL[tid] = 0.f; }
    __syncthreads();

    for (int kt = 0; kt <= qt; kt++) {
        const int kbase = kt * 64;

#pragma unroll
        for (int p = 0; p < 2; p++) {
            int id = p * 256 + tid;
            int r = id >> 3, c8 = (id & 7) * 8;
            size_t go = (size_t)(kbase + r) * DDM + c8;
            *(float4*)&sKh[r * ALD + c8] = *(const float4*)&khg[go];
            *(float4*)&sKl[r * ALD + c8] = *(const float4*)&klg[go];
            *(float4*)&sVh[r * ALD + c8] = *(const float4*)&vhg[go];
            *(float4*)&sVl[r * ALD + c8] = *(const float4*)&vlg[go];
        }
        __syncthreads();

        // S = Q K^T
        {
            wmma::fragment<wmma::accumulator, 16, 16, 16, float> s_acc[2];
            wmma::fill_fragment(s_acc[0], 0.0f);
            wmma::fill_fragment(s_acc[1], 0.0f);
#pragma unroll
            for (int kk = 0; kk < 4; kk++) {
                wmma::fragment<wmma::matrix_a, 16, 16, 16, __half, wmma::row_major> a_h, a_l;
                wmma::load_matrix_sync(a_h, sQh + (wm * 16) * ALD + kk * 16, ALD);
                wmma::load_matrix_sync(a_l, sQl + (wm * 16) * ALD + kk * 16, ALD);
#pragma unroll
                for (int j = 0; j < 2; j++) {
                    wmma::fragment<wmma::matrix_b, 16, 16, 16, __half, wmma::col_major> b_h, b_l;
                    const int co = (wn * 32 + j * 16) * ALD + kk * 16;
                    wmma::load_matrix_sync(b_h, sKh + co, ALD);
                    wmma::load_matrix_sync(b_l, sKl + co, ALD);
                    wmma::mma_sync(s_acc[j], a_h, b_h, s_acc[j]);
                    wmma::mma_sync(s_acc[j], a_h, b_l, s_acc[j]);
                    wmma::mma_sync(s_acc[j], a_l, b_h, s_acc[j]);
                }
            }
#pragma unroll
            for (int j = 0; j < 2; j++)
                wmma::store_matrix_sync(sS + (wm * 16) * FLD + wn * 32 + j * 16,
                                        s_acc[j], FLD, wmma::mem_row_major);
        }
        __syncthreads();

        // Softmax (4 threads per row, 16 cols each)
        {
            const int row = tid >> 2, q = tid & 3;
            float vals[16];
#pragma unroll
            for (int i = 0; i < 4; i++) {
                float4 v4 = *(float4*)&sS[row * FLD + q * 16 + i * 4];
                vals[i * 4 + 0] = v4.x; vals[i * 4 + 1] = v4.y;
                vals[i * 4 + 2] = v4.z; vals[i * 4 + 3] = v4.w;
            }
#pragma unroll
            for (int i = 0; i < 16; i++) vals[i] *= 0.125f;
            if (kt == qt) {
#pragma unroll
                for (int i = 0; i < 16; i++)
                    if (q * 16 + i > row) vals[i] = -INFINITY;
            }
            float mx = vals[0];
#pragma unroll
            for (int i = 1; i < 16; i++) mx = fmaxf(mx, vals[i]);
            mx = fmaxf(mx, __shfl_xor_sync(0xffffffffu, mx, 1));
            mx = fmaxf(mx, __shfl_xor_sync(0xffffffffu, mx, 2));
            const float mold = sM[row];
            const float mnew = fmaxf(mold, mx);
            float sum = 0.f;
            __half ph[16], pl[16];
#pragma unroll
            for (int i = 0; i < 16; i++) {
                float p = __expf(vals[i] - mnew);
                sum += p;
                ph[i] = __float2half(p);
                pl[i] = __float2half(p - __half2float(ph[i]));
            }
            sum += __shfl_xor_sync(0xffffffffu, sum, 1);
            sum += __shfl_xor_sync(0xffffffffu, sum, 2);
            const float alpha = __expf(mold - mnew);
#pragma unroll
            for (int i = 0; i < 4; i++) {
                float4 o4 = *(float4*)&sO[row * FLD + q * 16 + i * 4];
                o4.x *= alpha; o4.y *= alpha; o4.z *= alpha; o4.w *= alpha;
                *(float4*)&sO[row * FLD + q * 16 + i * 4] = o4;
            }
            *(float4*)&sPh[row * ALD + q * 16 + 0] = *(float4*)&ph[0];
            *(float4*)&sPh[row * ALD + q * 16 + 8] = *(float4*)&ph[8];
            *(float4*)&sPl[row * ALD + q * 16 + 0] = *(float4*)&pl[0];
            *(float4*)&sPl[row * ALD + q * 16 + 8] = *(float4*)&pl[8];
            if (q == 0) {
                sL[row] = sL[row] * alpha + sum;
                sM[row] = mnew;
            }
        }
        __syncthreads();

        // O += P V
        {
            wmma::fragment<wmma::accumulator, 16, 16, 16, float> o_acc[2];
#pragma unroll
            for (int j = 0; j < 2; j++)
                wmma::load_matrix_sync(o_acc[j],
                                       sO + (wm * 16) * FLD + wn * 32 + j * 16,
                                       FLD, wmma::mem_row_major);
#pragma unroll
            for (int kk = 0; kk < 4; kk++) {
                wmma::fragment<wmma::matrix_a, 16, 16, 16, __half, wmma::row_major> a_h, a_l;
                wmma::load_matrix_sync(a_h, sPh + (wm * 16) * ALD + kk * 16, ALD);
                wmma::load_matrix_sync(a_l, sPl + (wm * 16) * ALD + kk * 16, ALD);
#pragma unroll
                for (int j = 0; j < 2; j++) {
                    wmma::fragment<wmma::matrix_b, 16, 16, 16, __half, wmma::row_major> b_h, b_l;
                    const int vo = (kk * 16) * ALD + wn * 32 + j * 16;
                    wmma::load_matrix_sync(b_h, sVh + vo, ALD);
                    wmma::load_matrix_sync(b_l, sVl + vo, ALD);
                    wmma::mma_sync(o_acc[j], a_h, b_h, o_acc[j]);
                    wmma::mma_sync(o_acc[j], a_h, b_l, o_acc[j]);
                    wmma::mma_sync(o_acc[j], a_l, b_h, o_acc[j]);
                }
            }
#pragma unroll
            for (int j = 0; j < 2; j++)
                wmma::store_matrix_sync(sO + (wm * 16) * FLD + wn * 32 + j * 16,
                                        o_acc[j], FLD, wmma::mem_row_major);
        }
        __syncthreads();
    }

    // Epilogue: normalize and write hi/lo fp16 O
    {
        const int row = tid >> 2, q = tid & 3;
        const float inv = 1.0f / sL[row];
        __half hh[16], ll[16];
#pragma unroll
        for (int i = 0; i < 4; i++) {
            float4 o4 = *(float4*)&sO[row * FLD + q * 16 + i * 4];
            float vv[4] = {o4.x * inv, o4.y * inv, o4.z * inv, o4.w * inv};
#pragma unroll
            for (int u = 0; u < 4; u++) {
                hh[i * 4 + u] = __float2half(vv[u]);
                ll[i * 4 + u] = __float2half(vv[u] - __half2float(hh[i * 4 + u]));
            }
        }
        size_t off = (size_t)(b * LL + qbase + row) * DDM + h * DKK + q * 16;
        *(float4*)&g_ah[off + 0] = *(float4*)&hh[0];
        *(float4*)&g_ah[off + 8] = *(float4*)&hh[8];
        *(float4*)&g_al[off + 0] = *(float4*)&ll[0];
        *(float4*)&g_al[off + 8] = *(float4*)&ll[8];
    }
}

// ---------------------------------------------------------------------------
// Inputs (metadata order): Q, K, V, mask, Wq, bq, Wk, bk, Wv, bv, Wo, bo.
// ---------------------------------------------------------------------------
extern "C" void kernel_launch(void* const* d_in, const int* in_sizes, int n_in,
                              void* d_out, int out_size)
{
    const float* Q  = (const float*)d_in[0];
    const float* K  = (const float*)d_in[1];
    const float* V  = (const float*)d_in[2];
    const float* Wq = (const float*)d_in[4];
    const float* bq = (const float*)d_in[5];
    const float* Wk = (const float*)d_in[6];
    const float* bk = (const float*)d_in[7];
    const float* Wv = (const float*)d_in[8];
    const float* bv = (const float*)d_in[9];
    const float* Wo = (const float*)d_in[10];
    const float* bo = (const float*)d_in[11];
    float* out = (float*)d_out;

    cudaFuncSetAttribute(qkv_wmma_kernel,
                         cudaFuncAttributeMaxDynamicSharedMemorySize, SMEM_GEMM_BYTES);
    cudaFuncSetAttribute(out_wmma_kernel,
                         cudaFuncAttributeMaxDynamicSharedMemorySize, SMEM_GEMM_BYTES);
    cudaFuncSetAttribute(attn_wmma_kernel,
                         cudaFuncAttributeMaxDynamicSharedMemorySize, ATTN_SMEM_BYTES);

    const int nW4 = DDM * DDM / 4;

    cvt_kernel<<<nW4 / 256, 256>>>(Wq, 0, nW4);
    cvt_kernel<<<nW4 / 256, 256>>>(Wk, 1, nW4);
    cvt_kernel<<<nW4 / 256, 256>>>(Wv, 2, nW4);
    cvt_kernel<<<nW4 / 256, 256>>>(Wo, 3, nW4);

    dim3 gqkv(DDM / 128, MMR / 128, 3);
    qkv_wmma_kernel<<<gqkv, 256, SMEM_GEMM_BYTES>>>(Q, K, V, bq, bk, bv);

    dim3 gattn(LL / 64, BB * HH);
    attn_wmma_kernel<<<gattn, 256, ATTN_SMEM_BYTES>>>();

    dim3 gout(DDM / 128, MMR / 128);
    out_wmma_kernel<<<gout, 256, SMEM_GEMM_BYTES>>>(bo, out);
}

// round 7
// speedup vs baseline: 2.3218x; 1.1575x over previous
#include <cuda_runtime.h>
#include <cuda_fp16.h>
#include <mma.h>
#include <math.h>
#include <stdint.h>

using namespace nvcuda;

// Problem constants
#define BB  2
#define LL  2048
#define DDM 1024
#define HH  16
#define DKK 64
#define MMR (BB * LL)      // 4096 rows

// ---------------- scratch (device globals; no allocation allowed) ----------
__device__ __half g_wqh[(size_t)DDM * DDM], g_wql[(size_t)DDM * DDM];
__device__ __half g_wkh[(size_t)DDM * DDM], g_wkl[(size_t)DDM * DDM];
__device__ __half g_wvh[(size_t)DDM * DDM], g_wvl[(size_t)DDM * DDM];
__device__ __half g_woh[(size_t)DDM * DDM], g_wol[(size_t)DDM * DDM];
__device__ __half g_pqh[(size_t)MMR * DDM], g_pql[(size_t)MMR * DDM];
__device__ __half g_pkh[(size_t)MMR * DDM], g_pkl[(size_t)MMR * DDM];
__device__ __half g_pvh[(size_t)MMR * DDM], g_pvl[(size_t)MMR * DDM];
__device__ __half g_ah[(size_t)MMR * DDM],  g_al[(size_t)MMR * DDM];

// ---------------- helpers ---------------------------------------------------
__device__ __forceinline__ uint32_t smem_u32(const void* p) {
    uint32_t a;
    asm("{ .reg .u64 t; cvta.to.shared.u64 t, %1; cvt.u32.u64 %0, t; }"
        : "=r"(a) : "l"(p));
    return a;
}
__device__ __forceinline__ uint32_t f22h2(float x, float y) {
    __half2 h = __floats2half2_rn(x, y);
    return *reinterpret_cast<uint32_t*>(&h);
}
__device__ __forceinline__ float2 h22f2(uint32_t u) {
    __half2 h = *reinterpret_cast<__half2*>(&u);
    return __half22float2(h);
}
__device__ __forceinline__ void ldsm_x4(uint32_t* d, uint32_t addr) {
    asm volatile("ldmatrix.sync.aligned.m8n8.x4.shared.b16 {%0,%1,%2,%3}, [%4];"
                 : "=r"(d[0]), "=r"(d[1]), "=r"(d[2]), "=r"(d[3]) : "r"(addr));
}
__device__ __forceinline__ void ldsm_x4_t(uint32_t* d, uint32_t addr) {
    asm volatile("ldmatrix.sync.aligned.m8n8.x4.trans.shared.b16 {%0,%1,%2,%3}, [%4];"
                 : "=r"(d[0]), "=r"(d[1]), "=r"(d[2]), "=r"(d[3]) : "r"(addr));
}
__device__ __forceinline__ void mma16816(float* d, const uint32_t* a,
                                         uint32_t b0, uint32_t b1) {
    asm volatile("mma.sync.aligned.m16n8k16.row.col.f32.f16.f16.f32 "
                 "{%0,%1,%2,%3}, {%4,%5,%6,%7}, {%8,%9}, {%0,%1,%2,%3};"
                 : "+f"(d[0]), "+f"(d[1]), "+f"(d[2]), "+f"(d[3])
                 : "r"(a[0]), "r"(a[1]), "r"(a[2]), "r"(a[3]), "r"(b0), "r"(b1));
}
__device__ __forceinline__ void cp16(uint32_t saddr, const void* gaddr) {
    asm volatile("cp.async.cg.shared.global [%0], [%1], 16;"
                 :: "r"(saddr), "l"(gaddr));
}

// ---------------- fp32 -> fp16 hi/lo split (weights; one launch) ------------
__global__ __launch_bounds__(256) void cvt_kernel(
    const float* __restrict__ Wq, const float* __restrict__ Wk,
    const float* __restrict__ Wv, const float* __restrict__ Wo, int n4)
{
    const float* x;
    __half *hi, *lo;
    switch (blockIdx.y) {
        case 0: x = Wq; hi = g_wqh; lo = g_wql; break;
        case 1: x = Wk; hi = g_wkh; lo = g_wkl; break;
        case 2: x = Wv; hi = g_wvh; lo = g_wvl; break;
        default: x = Wo; hi = g_woh; lo = g_wol; break;
    }
    int i = blockIdx.x * blockDim.x + threadIdx.x;
    if (i >= n4) return;
    float4 v = ((const float4*)x)[i];
    __half h0 = __float2half(v.x), h1 = __float2half(v.y);
    __half h2 = __float2half(v.z), h3 = __float2half(v.w);
    __half l0 = __float2half(v.x - __half2float(h0));
    __half l1 = __float2half(v.y - __half2float(h1));
    __half l2 = __float2half(v.z - __half2float(h2));
    __half l3 = __float2half(v.w - __half2float(h3));
    ((__half2*)hi)[i * 2 + 0] = __halves2half2(h0, h1);
    ((__half2*)hi)[i * 2 + 1] = __halves2half2(h2, h3);
    ((__half2*)lo)[i * 2 + 0] = __halves2half2(l0, l1);
    ((__half2*)lo)[i * 2 + 1] = __halves2half2(l2, l3);
}

// ---------------- WMMA GEMM (unchanged from R5; known good) -----------------
#define LDHW 72
#define A_TILE (128 * LDHW)
#define SMEM_GEMM_BYTES (4 * A_TILE * 2)

__device__ __forceinline__ void split8(const float4& a, const float4& b,
                                       __half* hh, __half* ll)
{
    float v[8] = {a.x, a.y, a.z, a.w, b.x, b.y, b.z, b.w};
#pragma unroll
    for (int u = 0; u < 8; u++) {
        hh[u] = __float2half(v[u]);
        ll[u] = __float2half(v[u] - __half2float(hh[u]));
    }
}

template<bool A_FP32, bool HALF_OUT>
__device__ __forceinline__ void wmma_gemm(
    const float* __restrict__ Af,
    const __half* __restrict__ Ah, const __half* __restrict__ Al,
    const __half* __restrict__ Wh, const __half* __restrict__ Wl,
    const float* __restrict__ bias, float* __restrict__ Cf,
    __half* __restrict__ Ch, __half* __restrict__ Cl)
{
    extern __shared__ char smem[];
    __half* sAh = (__half*)smem;
    __half* sAl = sAh + A_TILE;
    __half* sWh = sAl + A_TILE;
    __half* sWl = sWh + A_TILE;

    const int tid  = threadIdx.x;
    const int w    = tid >> 5, lane = tid & 31;
    const int wm   = w & 3, wn = w >> 2;
    const int m0   = blockIdx.y * 128;
    const int n0   = blockIdx.x * 128;

    wmma::fragment<wmma::accumulator, 16, 16, 16, float> acc[2][4];
#pragma unroll
    for (int i = 0; i < 2; i++)
#pragma unroll
        for (int j = 0; j < 4; j++) wmma::fill_fragment(acc[i][j], 0.0f);

    for (int c = 0; c < 16; c++) {
        const int k0 = c * 64;
        float4 abuf[8];
        float4 wbuf[8];
        if (A_FP32) {
#pragma unroll
            for (int i = 0; i < 4; i++) {
                int id = i * 256 + tid;
                int r = id >> 3, q = id & 7;
                const float* ap = &Af[(size_t)(m0 + r) * DDM + k0 + q * 8];
                abuf[i * 2 + 0] = *(const float4*)ap;
                abuf[i * 2 + 1] = *(const float4*)(ap + 4);
            }
        } else {
#pragma unroll
            for (int i = 0; i < 4; i++) {
                int id = i * 256 + tid;
                int r = id >> 3, q = id & 7;
                abuf[i]     = *(const float4*)&Ah[(size_t)(m0 + r) * DDM + k0 + q * 8];
                abuf[4 + i] = *(const float4*)&Al[(size_t)(m0 + r) * DDM + k0 + q * 8];
            }
        }
#pragma unroll
        for (int i = 0; i < 4; i++) {
            int id = i * 256 + tid;
            int r = id >> 3, q = id & 7;
            wbuf[i]     = *(const float4*)&Wh[(size_t)(n0 + r) * DDM + k0 + q * 8];
            wbuf[4 + i] = *(const float4*)&Wl[(size_t)(n0 + r) * DDM + k0 + q * 8];
        }
        __syncthreads();
        if (A_FP32) {
#pragma unroll
            for (int i = 0; i < 4; i++) {
                int id = i * 256 + tid;
                int r = id >> 3, q = id & 7;
                __half hh[8], ll[8];
                split8(abuf[i * 2 + 0], abuf[i * 2 + 1], hh, ll);
                *(float4*)&sAh[r * LDHW + q * 8] = *(float4*)hh;
                *(float4*)&sAl[r * LDHW + q * 8] = *(float4*)ll;
            }
        } else {
#pragma unroll
            for (int i = 0; i < 4; i++) {
                int id = i * 256 + tid;
                int r = id >> 3, q = id & 7;
                *(float4*)&sAh[r * LDHW + q * 8] = abuf[i];
                *(float4*)&sAl[r * LDHW + q * 8] = abuf[4 + i];
            }
        }
#pragma unroll
        for (int i = 0; i < 4; i++) {
            int id = i * 256 + tid;
            int r = id >> 3, q = id & 7;
            *(float4*)&sWh[r * LDHW + q * 8] = wbuf[i];
            *(float4*)&sWl[r * LDHW + q * 8] = wbuf[4 + i];
        }
        __syncthreads();

#pragma unroll
        for (int kk = 0; kk < 4; kk++) {
            wmma::fragment<wmma::matrix_a, 16, 16, 16, __half, wmma::row_major> a_h[2], a_l[2];
#pragma unroll
            for (int i = 0; i < 2; i++) {
                const int ro = (wm * 32 + i * 16) * LDHW + kk * 16;
                wmma::load_matrix_sync(a_h[i], sAh + ro, LDHW);
                wmma::load_matrix_sync(a_l[i], sAl + ro, LDHW);
            }
#pragma unroll
            for (int j = 0; j < 4; j++) {
                wmma::fragment<wmma::matrix_b, 16, 16, 16, __half, wmma::col_major> b_h, b_l;
                const int co = (wn * 64 + j * 16) * LDHW + kk * 16;
                wmma::load_matrix_sync(b_h, sWh + co, LDHW);
                wmma::load_matrix_sync(b_l, sWl + co, LDHW);
#pragma unroll
                for (int i = 0; i < 2; i++) {
                    wmma::mma_sync(acc[i][j], a_h[i], b_h, acc[i][j]);
                    wmma::mma_sync(acc[i][j], a_h[i], b_l, acc[i][j]);
                    wmma::mma_sync(acc[i][j], a_l[i], b_h, acc[i][j]);
                }
            }
        }
    }

    __syncthreads();
    float* stage = (float*)smem + w * (32 * 68);
#pragma unroll
    for (int i = 0; i < 2; i++)
#pragma unroll
        for (int j = 0; j < 4; j++)
            wmma::store_matrix_sync(stage + i * 16 * 68 + j * 16, acc[i][j],
                                    68, wmma::mem_row_major);
    __syncwarp();

    const int col4 = (lane & 15) * 4;
    const int rb   = lane >> 4;
    const int ng   = n0 + wn * 64 + col4;
    float4 b4 = *(const float4*)&bias[ng];
#pragma unroll
    for (int r = 0; r < 16; r++) {
        int row = rb + r * 2;
        float4 v = *(float4*)&stage[row * 68 + col4];
        v.x += b4.x; v.y += b4.y; v.z += b4.z; v.w += b4.w;
        size_t off = (size_t)(m0 + wm * 32 + row) * DDM + ng;
        if (HALF_OUT) {
            __half hh[4], ll[4];
            hh[0] = __float2half(v.x); ll[0] = __float2half(v.x - __half2float(hh[0]));
            hh[1] = __float2half(v.y); ll[1] = __float2half(v.y - __half2float(hh[1]));
            hh[2] = __float2half(v.z); ll[2] = __float2half(v.z - __half2float(hh[2]));
            hh[3] = __float2half(v.w); ll[3] = __float2half(v.w - __half2float(hh[3]));
            *(uint2*)&Ch[off] = *(uint2*)hh;
            *(uint2*)&Cl[off] = *(uint2*)ll;
        } else {
            *(float4*)&Cf[off] = v;
        }
    }
}

__global__ __launch_bounds__(256) void qkv_wmma_kernel(
    const float* __restrict__ Q, const float* __restrict__ K,
    const float* __restrict__ V,
    const float* __restrict__ bq, const float* __restrict__ bk,
    const float* __restrict__ bv)
{
    if (blockIdx.z == 0)
        wmma_gemm<true, true>(Q, nullptr, nullptr, g_wqh, g_wql, bq,
                              nullptr, g_pqh, g_pql);
    else if (blockIdx.z == 1)
        wmma_gemm<true, true>(K, nullptr, nullptr, g_wkh, g_wkl, bk,
                              nullptr, g_pkh, g_pkl);
    else
        wmma_gemm<true, true>(V, nullptr, nullptr, g_wvh, g_wvl, bv,
                              nullptr, g_pvh, g_pvl);
}

__global__ __launch_bounds__(256) void out_wmma_kernel(
    const float* __restrict__ bo, float* __restrict__ out)
{
    wmma_gemm<false, false>(nullptr, g_ah, g_al, g_woh, g_wol, bo,
                            out, nullptr, nullptr);
}

// ---------------------------------------------------------------------------
// FA-2 attention with raw mma.m16n8k16. CTA = 128 q-rows of one (b,h).
// 8 warps, warp w owns rows w*16..w*16+15, full d=64 output in registers.
// kv tiles of 64; K/V (hi/lo) double-buffered via cp.async.
// ---------------------------------------------------------------------------
#define KLD 72
#define KVBUF (4 * 64 * KLD)            // halves per stage
#define ATTN_SMEM_BYTES (2 * KVBUF * 2) // 73728 bytes

__global__ __launch_bounds__(256) void attn_mma_kernel()
{
    extern __shared__ __half spool[];
    const int tid  = threadIdx.x;
    const int w    = tid >> 5, lane = tid & 31;
    const int g    = lane >> 2, tg = lane & 3;
    const int qblk = gridDim.x - 1 - blockIdx.x;    // big tiles first
    const int bh   = blockIdx.y;
    const int b    = bh >> 4, h = bh & 15;
    const int qbase = qblk * 128;
    const int r0    = w * 16;
    const int ntiles = 2 * qblk + 2;

    const size_t headoff = (size_t)b * LL * DDM + (size_t)h * DKK;
    const __half* qhg = g_pqh + headoff;
    const __half* qlg = g_pql + headoff;
    const __half* khg = g_pkh + headoff;
    const __half* klg = g_pkl + headoff;
    const __half* vhg = g_pvh + headoff;
    const __half* vlg = g_pvl + headoff;

    const uint32_t pool_u = smem_u32(spool);

    // ---- stage Q (scaled by 1/8, exact) and load fragments ----
    {
        __half* sQh = spool;                 // 128 x KLD
        __half* sQl = spool + 128 * KLD;
        const __half2 sc = __float2half2_rn(0.125f);
#pragma unroll
        for (int p = 0; p < 2; p++) {
            int id = p * 256 + tid;
            int r = id >> 2, c16 = (id & 3) * 16;
#pragma unroll
            for (int u = 0; u < 2; u++) {
                float4 vh = *(const float4*)&qhg[(size_t)(qbase + r) * DDM + c16 + u * 8];
                float4 vl = *(const float4*)&qlg[(size_t)(qbase + r) * DDM + c16 + u * 8];
                __half2* hp = (__half2*)&vh;
                __half2* lp = (__half2*)&vl;
#pragma unroll
                for (int e = 0; e < 4; e++) {
                    hp[e] = __hmul2(hp[e], sc);
                    lp[e] = __hmul2(lp[e], sc);
                }
                *(float4*)&sQh[r * KLD + c16 + u * 8] = vh;
                *(float4*)&sQl[r * KLD + c16 + u * 8] = vl;
            }
        }
    }
    __syncthreads();

    uint32_t qfh[4][4], qfl[4][4];
    {
        uint32_t qoff = ((uint32_t)(r0 + (lane & 15)) * KLD + (lane >> 4) * 8) * 2;
#pragma unroll
        for (int kk = 0; kk < 4; kk++) {
            ldsm_x4(qfh[kk], pool_u + qoff + kk * 32);
            ldsm_x4(qfl[kk], pool_u + (uint32_t)(128 * KLD) * 2 + qoff + kk * 32);
        }
    }
    __syncthreads();   // Q frags in regs; smem reusable

    // K/V stage offsets (halves) within a buffer
    const uint32_t oKh = 0, oKl = 64 * KLD, oVh = 2 * 64 * KLD, oVl = 3 * 64 * KLD;

    // cp.async: per thread loads row r = tid>>2, cols c16, c16+8 of each array
    const int ld_r  = tid >> 2;
    const int ld_c  = (tid & 3) * 16;
    const uint32_t sObase = ((uint32_t)ld_r * KLD + ld_c) * 2;

    auto issue_tile = [&](int kt, int buf) {
        const size_t go = (size_t)(kt * 64 + ld_r) * DDM + ld_c;
        const uint32_t sb = pool_u + (uint32_t)buf * KVBUF * 2 + sObase;
        cp16(sb + oKh * 2,      khg + go);
        cp16(sb + oKh * 2 + 16, khg + go + 8);
        cp16(sb + oKl * 2,      klg + go);
        cp16(sb + oKl * 2 + 16, klg + go + 8);
        cp16(sb + oVh * 2,      vhg + go);
        cp16(sb + oVh * 2 + 16, vhg + go + 8);
        cp16(sb + oVl * 2,      vlg + go);
        cp16(sb + oVl * 2 + 16, vlg + go + 8);
        asm volatile("cp.async.commit_group;");
    };

    // ldsm lane bases
    const uint32_t kbasea = (((lane & 7) + ((lane >> 4) << 3)) * KLD +
                             ((lane >> 3) & 1) * 8) * 2;
    const uint32_t vbasea = ((lane & 15) * KLD + (lane >> 4) * 8) * 2;

    float o[8][4];
#pragma unroll
    for (int jn = 0; jn < 8; jn++)
#pragma unroll
        for (int e = 0; e < 4; e++) o[jn][e] = 0.f;
    float m_a = -INFINITY, m_b = -INFINITY, l_a = 0.f, l_b = 0.f;

    issue_tile(0, 0);

    for (int kt = 0; kt < ntiles; kt++) {
        __syncthreads();   // everyone done reading buffer (kt+1)&1 (used at kt-1)
        if (kt + 1 < ntiles) {
            issue_tile(kt + 1, (kt + 1) & 1);
            asm volatile("cp.async.wait_group 1;");
        } else {
            asm volatile("cp.async.wait_group 0;");
        }
        __syncthreads();   // tile kt visible to all

        const uint32_t bufu = pool_u + (uint32_t)(kt & 1) * KVBUF * 2;
        const uint32_t ku_h = bufu + oKh * 2, ku_l = bufu + oKl * 2;
        const uint32_t vu_h = bufu + oVh * 2, vu_l = bufu + oVl * 2;

        // ---- S = Q K^T ----
        float s[8][4];
#pragma unroll
        for (int jn = 0; jn < 8; jn++)
#pragma unroll
            for (int e = 0; e < 4; e++) s[jn][e] = 0.f;

#pragma unroll
        for (int kk = 0; kk < 4; kk++) {
#pragma unroll
            for (int jp = 0; jp < 4; jp++) {
                const uint32_t koff = ((uint32_t)(jp * 16) * KLD + kk * 16) * 2;
                uint32_t bh_[4], bl_[4];
                ldsm_x4(bh_, ku_h + kbasea + koff);
                ldsm_x4(bl_, ku_l + kbasea + koff);
                mma16816(s[2 * jp],     qfh[kk], bh_[0], bh_[1]);
                mma16816(s[2 * jp],     qfh[kk], bl_[0], bl_[1]);
                mma16816(s[2 * jp],     qfl[kk], bh_[0], bh_[1]);
                mma16816(s[2 * jp + 1], qfh[kk], bh_[2], bh_[3]);
                mma16816(s[2 * jp + 1], qfh[kk], bl_[2], bl_[3]);
                mma16816(s[2 * jp + 1], qfl[kk], bh_[2], bh_[3]);
            }
        }

        // ---- causal mask (only tiles overlapping the diagonal) ----
        const int rowa = qbase + r0 + g;
        const int rowb = rowa + 8;
        if (kt >= 2 * qblk) {
            const int kb = kt * 64;
#pragma unroll
            for (int jn = 0; jn < 8; jn++) {
                const int c0 = kb + jn * 8 + tg * 2;
                if (c0     > rowa) s[jn][0] = -INFINITY;
                if (c0 + 1 > rowa) s[jn][1] = -INFINITY;
                if (c0     > rowb) s[jn][2] = -INFINITY;
                if (c0 + 1 > rowb) s[jn][3] = -INFINITY;
            }
        }

        // ---- online softmax (rows g, g+8; quad shfl reductions) ----
        float mxa = -INFINITY, mxb = -INFINITY;
#pragma unroll
        for (int jn = 0; jn < 8; jn++) {
            mxa = fmaxf(mxa, fmaxf(s[jn][0], s[jn][1]));
            mxb = fmaxf(mxb, fmaxf(s[jn][2], s[jn][3]));
        }
        mxa = fmaxf(mxa, __shfl_xor_sync(0xffffffffu, mxa, 1));
        mxa = fmaxf(mxa, __shfl_xor_sync(0xffffffffu, mxa, 2));
        mxb = fmaxf(mxb, __shfl_xor_sync(0xffffffffu, mxb, 1));
        mxb = fmaxf(mxb, __shfl_xor_sync(0xffffffffu, mxb, 2));
        const float mna = fmaxf(m_a, mxa);
        const float mnb = fmaxf(m_b, mxb);
        float suma = 0.f, sumb = 0.f;
#pragma unroll
        for (int jn = 0; jn < 8; jn++) {
            s[jn][0] = __expf(s[jn][0] - mna);
            s[jn][1] = __expf(s[jn][1] - mna);
            s[jn][2] = __expf(s[jn][2] - mnb);
            s[jn][3] = __expf(s[jn][3] - mnb);
            suma += s[jn][0] + s[jn][1];
            sumb += s[jn][2] + s[jn][3];
        }
        suma += __shfl_xor_sync(0xffffffffu, suma, 1);
        suma += __shfl_xor_sync(0xffffffffu, suma, 2);
        sumb += __shfl_xor_sync(0xffffffffu, sumb, 1);
        sumb += __shfl_xor_sync(0xffffffffu, sumb, 2);
        const float aa = __expf(m_a - mna);
        const float ab = __expf(m_b - mnb);
        m_a = mna; m_b = mnb;
        l_a = l_a * aa + suma;
        l_b = l_b * ab + sumb;
#pragma unroll
        for (int jn = 0; jn < 8; jn++) {
            o[jn][0] *= aa; o[jn][1] *= aa;
            o[jn][2] *= ab; o[jn][3] *= ab;
        }

        // ---- P fragments (hi/lo) directly from S accumulators ----
        uint32_t pah[4][4], pal[4][4];
#pragma unroll
        for (int jk = 0; jk < 4; jk++) {
            const int t0 = 2 * jk, t1 = t0 + 1;
            const float* p0 = s[t0];
            const float* p1 = s[t1];
            pah[jk][0] = f22h2(p0[0], p0[1]);
            pah[jk][1] = f22h2(p0[2], p0[3]);
            pah[jk][2] = f22h2(p1[0], p1[1]);
            pah[jk][3] = f22h2(p1[2], p1[3]);
            float2 r;
            r = h22f2(pah[jk][0]); pal[jk][0] = f22h2(p0[0] - r.x, p0[1] - r.y);
            r = h22f2(pah[jk][1]); pal[jk][1] = f22h2(p0[2] - r.x, p0[3] - r.y);
            r = h22f2(pah[jk][2]); pal[jk][2] = f22h2(p1[0] - r.x, p1[1] - r.y);
            r = h22f2(pah[jk][3]); pal[jk][3] = f22h2(p1[2] - r.x, p1[3] - r.y);
        }

        // ---- O += P V ----
#pragma unroll
        for (int jk = 0; jk < 4; jk++) {
#pragma unroll
            for (int jp = 0; jp < 4; jp++) {
                const uint32_t voff = ((uint32_t)(jk * 16) * KLD + jp * 16) * 2;
                uint32_t bh_[4], bl_[4];
                ldsm_x4_t(bh_, vu_h + vbasea + voff);
                ldsm_x4_t(bl_, vu_l + vbasea + voff);
                mma16816(o[2 * jp],     pah[jk], bh_[0], bh_[1]);
                mma16816(o[2 * jp],     pah[jk], bl_[0], bl_[1]);
                mma16816(o[2 * jp],     pal[jk], bh_[0], bh_[1]);
                mma16816(o[2 * jp + 1], pah[jk], bh_[2], bh_[3]);
                mma16816(o[2 * jp + 1], pah[jk], bl_[2], bl_[3]);
                mma16816(o[2 * jp + 1], pal[jk], bh_[2], bh_[3]);
            }
        }
    }

    // ---- epilogue: normalize, split hi/lo, store ----
    {
        const float inva = 1.f / l_a;
        const float invb = 1.f / l_b;
        const int rowa = qbase + r0 + g;
        const size_t basea = (size_t)(b * LL + rowa) * DDM + h * DKK;
        const size_t baseb = basea + (size_t)8 * DDM;
#pragma unroll
        for (int jn = 0; jn < 8; jn++) {
            const int c = jn * 8 + tg * 2;
            float v0 = o[jn][0] * inva, v1 = o[jn][1] * inva;
            uint32_t hh = f22h2(v0, v1);
            float2 hf = h22f2(hh);
            uint32_t ll = f22h2(v0 - hf.x, v1 - hf.y);
            *(uint32_t*)&g_ah[basea + c] = hh;
            *(uint32_t*)&g_al[basea + c] = ll;
            v0 = o[jn][2] * invb; v1 = o[jn][3] * invb;
            hh = f22h2(v0, v1);
            hf = h22f2(hh);
            ll = f22h2(v0 - hf.x, v1 - hf.y);
            *(uint32_t*)&g_ah[baseb + c] = hh;
            *(uint32_t*)&g_al[baseb + c] = ll;
        }
    }
}

// ---------------------------------------------------------------------------
// Inputs (metadata order): Q, K, V, mask, Wq, bq, Wk, bk, Wv, bv, Wo, bo.
// ---------------------------------------------------------------------------
extern "C" void kernel_launch(void* const* d_in, const int* in_sizes, int n_in,
                              void* d_out, int out_size)
{
    const float* Q  = (const float*)d_in[0];
    const float* K  = (const float*)d_in[1];
    const float* V  = (const float*)d_in[2];
    const float* Wq = (const float*)d_in[4];
    const float* bq = (const float*)d_in[5];
    const float* Wk = (const float*)d_in[6];
    const float* bk = (const float*)d_in[7];
    const float* Wv = (const float*)d_in[8];
    const float* bv = (const float*)d_in[9];
    const float* Wo = (const float*)d_in[10];
    const float* bo = (const float*)d_in[11];
    float* out = (float*)d_out;

    cudaFuncSetAttribute(qkv_wmma_kernel,
                         cudaFuncAttributeMaxDynamicSharedMemorySize, SMEM_GEMM_BYTES);
    cudaFuncSetAttribute(out_wmma_kernel,
                         cudaFuncAttributeMaxDynamicSharedMemorySize, SMEM_GEMM_BYTES);
    cudaFuncSetAttribute(attn_mma_kernel,
                         cudaFuncAttributeMaxDynamicSharedMemorySize, ATTN_SMEM_BYTES);

    const int nW4 = DDM * DDM / 4;

    dim3 gcvt(nW4 / 256, 4);
    cvt_kernel<<<gcvt, 256>>>(Wq, Wk, Wv, Wo, nW4);

    dim3 gqkv(DDM / 128, MMR / 128, 3);
    qkv_wmma_kernel<<<gqkv, 256, SMEM_GEMM_BYTES>>>(Q, K, V, bq, bk, bv);

    dim3 gattn(LL / 128, BB * HH);
    attn_mma_kernel<<<gattn, 256, ATTN_SMEM_BYTES>>>();

    dim3 gout(DDM / 128, MMR / 128);
    out_wmma_kernel<<<gout, 256, SMEM_GEMM_BYTES>>>(bo, out);
}